// round 13
// baseline (speedup 1.0000x reference)
#include <cuda_runtime.h>
#include <cuda_bf16.h>
#include <math.h>
#include <stdint.h>

// ---------------- problem constants ----------------
#define NN    8192
#define KNB   32
#define CLd   384
#define CPd   128
#define Hh    4
#define Sd    32
#define Pp    8
#define PROJ  336
#define NPAD  384
#define CONC  736
#define KP2   768

// ---------------- scratch (device globals; no allocation) ----------------
__device__ __align__(16) __nv_bfloat16 g_Lhi[NN * CLd];
__device__ __align__(16) __nv_bfloat16 g_Llo[NN * CLd];
__device__ __align__(16) __nv_bfloat16 g_WpT_hi[NPAD * CLd];
__device__ __align__(16) __nv_bfloat16 g_WpT_lo[NPAD * CLd];
__device__ __align__(16) float         g_biasp[NPAD];
__device__ __align__(16) __nv_bfloat16 g_WoT_hi[NPAD * KP2];
__device__ __align__(16) __nv_bfloat16 g_WoT_lo[NPAD * KP2];
__device__ __align__(16) __nv_bfloat16 g_Chi[NN * KP2];
__device__ __align__(16) __nv_bfloat16 g_Clo[NN * KP2];
__device__ __align__(16) float g_proj[NN * NPAD];
__device__ __align__(16) float g_q [NN * 128];
__device__ __align__(16) float g_k [NN * 32];
__device__ __align__(16) float g_v [NN * 32];
__device__ __align__(16) float g_qp[NN * 96];
__device__ __align__(16) float g_kp[NN * 24];
__device__ __align__(16) float g_vp[NN * 24];

// ---------------- PTX helpers ----------------
__device__ __forceinline__ uint32_t smem_u32(const void* p) {
    uint32_t a;
    asm("{ .reg .u64 t; cvta.to.shared.u64 t, %1; cvt.u32.u64 %0, t; }" : "=r"(a) : "l"(p));
    return a;
}

#define CP16(dst, src) \
    asm volatile("cp.async.cg.shared.global [%0], [%1], 16;" :: "r"(dst), "l"(src))
#define CP_COMMIT() asm volatile("cp.async.commit_group;" ::: "memory")
#define CP_WAIT(n)  asm volatile("cp.async.wait_group %0;" :: "n"(n) : "memory")

#define LDSM4(R, addr) \
    asm volatile("ldmatrix.sync.aligned.m8n8.x4.shared.b16 {%0,%1,%2,%3}, [%4];" \
        : "=r"((R)[0]), "=r"((R)[1]), "=r"((R)[2]), "=r"((R)[3]) : "r"(addr))

#define MMA16816(C, A, b0, b1) \
    asm volatile("mma.sync.aligned.m16n8k16.row.col.f32.bf16.bf16.f32 " \
        "{%0,%1,%2,%3}, {%4,%5,%6,%7}, {%8,%9}, {%0,%1,%2,%3};" \
        : "+f"((C)[0]), "+f"((C)[1]), "+f"((C)[2]), "+f"((C)[3]) \
        : "r"((A)[0]), "r"((A)[1]), "r"((A)[2]), "r"((A)[3]), "r"(b0), "r"(b1))

// ---------------- misc warp helpers ----------------
__device__ __forceinline__ float warp_sum(float v) {
#pragma unroll
    for (int o = 16; o; o >>= 1) v += __shfl_xor_sync(0xffffffffu, v, o);
    return v;
}
__device__ __forceinline__ float warp_max(float v) {
#pragma unroll
    for (int o = 16; o; o >>= 1) v = fmaxf(v, __shfl_xor_sync(0xffffffffu, v, o));
    return v;
}
__device__ __forceinline__ float2 warp_sum2(float a, float b) {
#pragma unroll
    for (int o = 16; o; o >>= 1) {
        a += __shfl_xor_sync(0xffffffffu, a, o);
        b += __shfl_xor_sync(0xffffffffu, b, o);
    }
    return make_float2(a, b);
}
__device__ __forceinline__ void st_hilo(__nv_bfloat16* hi, __nv_bfloat16* lo, size_t idx, float v) {
    __nv_bfloat16 h = __float2bfloat16(v);
    hi[idx] = h;
    lo[idx] = __float2bfloat16(v - __bfloat162float(h));
}

// ---------------- prep kernel 1: local hi/lo split + bias ----------------
__global__ void prep_local(
    const float* __restrict__ local,
    const float* __restrict__ bq,  const float* __restrict__ bk,
    const float* __restrict__ bv,  const float* __restrict__ bqp,
    const float* __restrict__ bkp, const float* __restrict__ bvp)
{
    const int total = NN * CLd;
    for (int idx = blockIdx.x * blockDim.x + threadIdx.x; idx < total;
         idx += gridDim.x * blockDim.x) {
        float v = local[idx];
        __nv_bfloat16 h = __float2bfloat16(v);
        g_Lhi[idx] = h;
        g_Llo[idx] = __float2bfloat16(v - __bfloat162float(h));
    }
    int idx = blockIdx.x * blockDim.x + threadIdx.x;
    if (idx < NPAD) {
        int n = idx;
        float b = 0.f;
        if      (n < 128) b = bq [n];
        else if (n < 160) b = bk [n - 128];
        else if (n < 192) b = bv [n - 160];
        else if (n < 288) b = bqp[n - 192];
        else if (n < 312) b = bkp[n - 288];
        else if (n < 336) b = bvp[n - 312];
        g_biasp[n] = b;
    }
}

// ---------------- prep kernel 2: Wproj transpose (coalesced, 32x32 tiles) ----------------
__global__ void __launch_bounds__(256) prep_wpt(
    const float* __restrict__ Wq,  const float* __restrict__ Wk,
    const float* __restrict__ Wv,  const float* __restrict__ Wqp,
    const float* __restrict__ Wkp, const float* __restrict__ Wvp)
{
    __shared__ float tile[32][33];
    const int n0 = blockIdx.x * 32, k0 = blockIdx.y * 32;
    const int tx = threadIdx.x, ty = threadIdx.y;
#pragma unroll
    for (int i = 0; i < 4; i++) {
        int k = k0 + ty + i * 8, n = n0 + tx;
        float w = 0.f;
        if      (n < 128) w = Wq [k * 128 + n];
        else if (n < 160) w = Wk [k * 32  + (n - 128)];
        else if (n < 192) w = Wv [k * 32  + (n - 160)];
        else if (n < 288) w = Wqp[k * 96  + (n - 192)];
        else if (n < 312) w = Wkp[k * 24  + (n - 288)];
        else if (n < 336) w = Wvp[k * 24  + (n - 312)];
        tile[ty + i * 8][tx] = w;
    }
    __syncthreads();
#pragma unroll
    for (int i = 0; i < 4; i++) {
        int n = n0 + ty + i * 8, k = k0 + tx;
        st_hilo(g_WpT_hi, g_WpT_lo, (size_t)n * CLd + k, tile[tx][ty + i * 8]);
    }
}

// ---------------- prep kernel 3: Wout transpose (coalesced, 32x32 tiles) ----------------
__global__ void __launch_bounds__(256) prep_wot(const float* __restrict__ Wout)
{
    __shared__ float tile[32][33];
    const int n0 = blockIdx.x * 32, k0 = blockIdx.y * 32;
    const int tx = threadIdx.x, ty = threadIdx.y;
#pragma unroll
    for (int i = 0; i < 4; i++) {
        int k = k0 + ty + i * 8, n = n0 + tx;
        float w = (k < CONC) ? Wout[(size_t)k * CLd + n] : 0.f;
        tile[ty + i * 8][tx] = w;
    }
    __syncthreads();
#pragma unroll
    for (int i = 0; i < 4; i++) {
        int n = n0 + ty + i * 8, k = k0 + tx;
        st_hilo(g_WoT_hi, g_WoT_lo, (size_t)n * KP2 + k, tile[tx][ty + i * 8]);
    }
}

// ---------------- HMMA GEMM: BM=128, BN=96, 256 threads, single-stage, 2 CTAs/SM ----------
// Stage: Ah(18432) Al(18432) Bh(13824) Bl(13824) = 64512 B.
#define STG2_BYTES 64512
#define OFF2_AL 18432
#define OFF2_BH 36864
#define OFF2_BL 50688

__device__ __forceinline__ void issue_tile2(uint32_t sdst, const __nv_bfloat16* __restrict__ src,
                                            int K, int kk8, int tid, int nchunks)
{
#pragma unroll
    for (int i = tid; i < nchunks; i += 256) {
        int r = i >> 3, c = i & 7;
        CP16(sdst + r * 144 + c * 16, src + (size_t)r * K + ((kk8 + c) << 3));
    }
}

__global__ void __launch_bounds__(256, 2) mma_gemm(
    const __nv_bfloat16* __restrict__ Ahi, const __nv_bfloat16* __restrict__ Alo,
    const __nv_bfloat16* __restrict__ Bhi, const __nv_bfloat16* __restrict__ Blo,
    const float* __restrict__ bias, float* __restrict__ C, int K)
{
    extern __shared__ char dsm[];
    const uint32_t sbase = smem_u32(dsm);
    const int tid  = threadIdx.x;
    const int lane = tid & 31;
    const int wid  = tid >> 5;          // 0..7
    const int wm   = wid >> 1;          // 0..3 (m)
    const int wn   = wid & 1;           // 0..1 (n)
    const int rowBase = blockIdx.y * 128;
    const int colBase = blockIdx.x * 96;
    const int NC = K >> 6;

    const __nv_bfloat16* pAh = Ahi + (size_t)rowBase * K;
    const __nv_bfloat16* pAl = Alo + (size_t)rowBase * K;
    const __nv_bfloat16* pBh = Bhi + (size_t)colBase * K;
    const __nv_bfloat16* pBl = Blo + (size_t)colBase * K;

    const uint32_t aoff = (uint32_t)((lane & 15) * 144 + ((lane >> 4) << 4));
    const int bmat = lane >> 3, brow = lane & 7;
    const uint32_t boff = (uint32_t)(((bmat & 1) * 8 + brow) * 144 + ((bmat >> 1) << 4));
    const uint32_t awbase = (uint32_t)(wm * 32 * 144);
    const uint32_t bwbase = (uint32_t)(wn * 48 * 144);

    float acc[2][6][4];
#pragma unroll
    for (int i = 0; i < 2; i++)
#pragma unroll
        for (int j = 0; j < 6; j++)
#pragma unroll
            for (int q = 0; q < 4; q++) acc[i][j][q] = 0.f;

    const uint32_t sAh = sbase + awbase;
    const uint32_t sAl = sbase + OFF2_AL + awbase;
    const uint32_t sBh = sbase + OFF2_BH + bwbase;
    const uint32_t sBl = sbase + OFF2_BL + bwbase;

    for (int i = 0; i < NC; i++) {
        int kk8 = i * 8;
        issue_tile2(sbase,            pAh, K, kk8, tid, 1024);
        issue_tile2(sbase + OFF2_AL,  pAl, K, kk8, tid, 1024);
        issue_tile2(sbase + OFF2_BH,  pBh, K, kk8, tid, 768);
        issue_tile2(sbase + OFF2_BL,  pBl, K, kk8, tid, 768);
        CP_COMMIT();
        CP_WAIT(0);
        __syncthreads();

#pragma unroll
        for (int ks = 0; ks < 4; ks++) {
            const uint32_t ka = (uint32_t)(ks * 32);
            uint32_t ah[8], al[8], bh[12], bl[12];
            LDSM4(ah,     sAh + ka + aoff);
            LDSM4(ah + 4, sAh + 16 * 144 + ka + aoff);
            LDSM4(al,     sAl + ka + aoff);
            LDSM4(al + 4, sAl + 16 * 144 + ka + aoff);
#pragma unroll
            for (int L = 0; L < 3; L++) {
                LDSM4(bh + L * 4, sBh + (uint32_t)(L * 16 * 144) + ka + boff);
                LDSM4(bl + L * 4, sBl + (uint32_t)(L * 16 * 144) + ka + boff);
            }
#pragma unroll
            for (int mf = 0; mf < 2; mf++) {
#pragma unroll
                for (int nt = 0; nt < 6; nt++) {
                    const int L = nt >> 1, h = nt & 1;
                    MMA16816(acc[mf][nt], ah + mf * 4, bh[L * 4 + h], bh[L * 4 + 2 + h]);
                    MMA16816(acc[mf][nt], ah + mf * 4, bl[L * 4 + h], bl[L * 4 + 2 + h]);
                    MMA16816(acc[mf][nt], al + mf * 4, bh[L * 4 + h], bh[L * 4 + 2 + h]);
                }
            }
        }
        __syncthreads();
    }

    const int r0 = lane >> 2;
    const int c0 = (lane & 3) * 2;
#pragma unroll
    for (int mf = 0; mf < 2; mf++) {
#pragma unroll
        for (int nt = 0; nt < 6; nt++) {
            int row = rowBase + wm * 32 + mf * 16 + r0;
            int col = colBase + wn * 48 + nt * 8 + c0;
            float b0 = 0.f, b1 = 0.f;
            if (bias) { b0 = bias[col]; b1 = bias[col + 1]; }
            float2 v0 = make_float2(acc[mf][nt][0] + b0, acc[mf][nt][1] + b1);
            float2 v1 = make_float2(acc[mf][nt][2] + b0, acc[mf][nt][3] + b1);
            *(float2*)(C + (size_t)row * NPAD + col)       = v0;
            *(float2*)(C + (size_t)(row + 8) * NPAD + col) = v1;
        }
    }
}

// ---------------- kernel: LN + frame transforms ----------------
__global__ void __launch_bounds__(256) proj_epilogue(const float* __restrict__ frames)
{
    const int warp = threadIdx.x >> 5;
    const int lane = threadIdx.x & 31;
    const int n = blockIdx.x * 8 + warp;
    if (n >= NN) return;
    const float* pr = g_proj + (size_t)n * NPAD;
    const float inv_sqrtS = 0.17677669529663687f;

#pragma unroll
    for (int h = 0; h < Hh; h++) {
        float x  = pr[h * 32 + lane];
        float2 s = warp_sum2(x, x * x);
        float mu = s.x * (1.f / 32.f);
        float var = s.y * (1.f / 32.f) - mu * mu;
        g_q[(size_t)n * 128 + h * 32 + lane] = (x - mu) * rsqrtf(var + 1e-5f) * inv_sqrtS;
    }
    {
        float x  = pr[128 + lane];
        float2 s = warp_sum2(x, x * x);
        float mu = s.x * (1.f / 32.f);
        float var = s.y * (1.f / 32.f) - mu * mu;
        g_k[(size_t)n * 32 + lane] = (x - mu) * rsqrtf(var + 1e-5f);
    }
    g_v[(size_t)n * 32 + lane] = pr[160 + lane];

    const float* fr = frames + (size_t)n * 16;
    float R00 = fr[0],  R01 = fr[1],  R02 = fr[2],  t0 = fr[3];
    float R10 = fr[4],  R11 = fr[5],  R12 = fr[6],  t1 = fr[7];
    float R20 = fr[8],  R21 = fr[9],  R22 = fr[10], t2 = fr[11];

    {
        float px = pr[192 + lane * 3 + 0];
        float py = pr[192 + lane * 3 + 1];
        float pz = pr[192 + lane * 3 + 2];
        float* q = g_qp + (size_t)n * 96 + lane * 3;
        q[0] = R00 * px + R01 * py + R02 * pz + t0;
        q[1] = R10 * px + R11 * py + R12 * pz + t1;
        q[2] = R20 * px + R21 * py + R22 * pz + t2;
    }
    if (lane < 8) {
        float px = pr[288 + lane * 3 + 0];
        float py = pr[288 + lane * 3 + 1];
        float pz = pr[288 + lane * 3 + 2];
        float* q = g_kp + (size_t)n * 24 + lane * 3;
        q[0] = R00 * px + R01 * py + R02 * pz + t0;
        q[1] = R10 * px + R11 * py + R12 * pz + t1;
        q[2] = R20 * px + R21 * py + R22 * pz + t2;
    } else if (lane < 16) {
        int l2 = lane - 8;
        float px = pr[312 + l2 * 3 + 0];
        float py = pr[312 + l2 * 3 + 1];
        float pz = pr[312 + l2 * 3 + 2];
        float* q = g_vp + (size_t)n * 24 + l2 * 3;
        q[0] = R00 * px + R01 * py + R02 * pz + t0;
        q[1] = R10 * px + R11 * py + R12 * pz + t1;
        q[2] = R20 * px + R21 * py + R22 * pz + t2;
    }
}

// ---------------- kernel: attention (R9 exact — measured 80.7us) ----------------
__global__ void __launch_bounds__(128, 8) attn_kernel(
    const float* __restrict__ pair,        // N*K*CP
    const int*   __restrict__ neighbours,  // N*K
    const float* __restrict__ frames,      // N*16
    const float* __restrict__ Wb,          // CP*H
    const float* __restrict__ gamma)       // H
{
    const int n    = blockIdx.x;
    const int t    = threadIdx.x;
    const int lane = t & 31;
    const int warp = t >> 5;

    __shared__ float s_q[128];
    __shared__ float s_qp[96];
    __shared__ int   s_nb[32];
    __shared__ float s_k [32][33];
    __shared__ float s_kp[32][25];
    __shared__ __align__(16) float s_pair[32 * 128];
    __shared__ __align__(16) float s_WbT[4 * 128];
    __shared__ __align__(16) float s_pb2[2 * 128];    // [half][k*4+h]
    __shared__ __align__(16) float s_attnT[32 * 4];   // [k][h]
    __shared__ float s_pt[96];

    // async pair load (16KB) — overlaps gathers
    {
        const uint32_t sp = smem_u32(s_pair);
        const float* psrc = pair + (size_t)n * 4096;
#pragma unroll
        for (int j = 0; j < 8; j++) {
            int i = t + 128 * j;
            CP16(sp + (uint32_t)i * 16, psrc + i * 4);
        }
        CP_COMMIT();
    }

    if (t < 32) s_nb[t] = neighbours[(size_t)n * 32 + t];
    s_q[t] = g_q[(size_t)n * 128 + t];
    if (t < 96) s_qp[t] = g_qp[(size_t)n * 96 + t];
    for (int i = t; i < 512; i += 128) {
        int c = i & 127, h = i >> 7;
        s_WbT[h * 128 + c] = Wb[c * 4 + h];
    }
    __syncthreads();   // s_nb ready

    // k gather
#pragma unroll
    for (int i = t; i < 256; i += 128) {
        int row = i >> 3, c4 = i & 7, nb = s_nb[row];
        float4 kv = *(const float4*)(g_k + (size_t)nb * 32 + c4 * 4);
        s_k[row][c4*4+0]=kv.x; s_k[row][c4*4+1]=kv.y; s_k[row][c4*4+2]=kv.z; s_k[row][c4*4+3]=kv.w;
    }
    // kp gather
#pragma unroll
    for (int i = t; i < 192; i += 128) {
        int row = i / 6, c4 = i % 6, nb = s_nb[row];
        float4 a4 = *(const float4*)(g_kp + (size_t)nb * 24 + c4 * 4);
        s_kp[row][c4*4+0]=a4.x; s_kp[row][c4*4+1]=a4.y; s_kp[row][c4*4+2]=a4.z; s_kp[row][c4*4+3]=a4.w;
    }
    CP_WAIT(0);
    __syncthreads();

    // pb partials: warp w -> heads {h0, h0+1}, column half [64*(w&1), +64).
    {
        const int half = warp & 1;
        const int h0   = (warp >> 1) << 1;
        const float4* prow = (const float4*)(s_pair + lane * 128 + half * 64);
        const float4* wr0  = (const float4*)(s_WbT + (h0 + 0) * 128 + half * 64);
        const float4* wr1  = (const float4*)(s_WbT + (h0 + 1) * 128 + half * 64);
        float pp0 = 0.f, pp1 = 0.f;
#pragma unroll
        for (int i = 0; i < 16; i++) {
            int c4 = (i + lane) & 15;
            float4 p  = prow[c4];
            float4 wa = wr0[c4];
            float4 wb = wr1[c4];
            pp0 += p.x * wa.x + p.y * wa.y + p.z * wa.z + p.w * wa.w;
            pp1 += p.x * wb.x + p.y * wb.y + p.z * wb.z + p.w * wb.w;
        }
        *(float2*)(s_pb2 + half * 128 + lane * 4 + h0) = make_float2(pp0, pp1);
    }
    __syncthreads();

    // ---- logits: head = warp, neighbour = lane ----
    const float w_L = 0.5773502691896258f;
    float gam   = gamma[warp];
    float scale = log1pf(__expf(gam)) * (1.0f / 6.0f) * 0.5f;

    float qk = 0.f;
#pragma unroll
    for (int s = 0; s < 32; s++) qk += s_q[warp * 32 + s] * s_k[lane][s];

    float dist = 0.f;
#pragma unroll
    for (int p = 0; p < 8; p++) {
        float dx = s_qp[warp * 24 + p * 3 + 0] - s_kp[lane][p * 3 + 0];
        float dy = s_qp[warp * 24 + p * 3 + 1] - s_kp[lane][p * 3 + 1];
        float dz = s_qp[warp * 24 + p * 3 + 2] - s_kp[lane][p * 3 + 2];
        dist += dx * dx + dy * dy + dz * dz;
    }

    float pb = s_pb2[lane * 4 + warp] + s_pb2[128 + lane * 4 + warp];

    float logit = w_L * (qk - scale * dist + pb);
    float m = warp_max(logit);
    float e = __expf(logit - m);
    float sm = warp_sum(e);
    s_attnT[lane * 4 + warp] = e / sm;    // [k][h]
    __syncthreads();

    const size_t cbase = (size_t)n * KP2;

    // local_up: (h=warp, s=lane); v streamed from gmem (lane-coalesced, L2-resident)
    {
        float acc = 0.f;
#pragma unroll
        for (int kk = 0; kk < 32; kk++)
            acc += s_attnT[kk * 4 + warp] * __ldg(g_v + (size_t)s_nb[kk] * 32 + lane);
        st_hilo(g_Chi, g_Clo, cbase + warp * 32 + lane, acc);
    }
    // pair_up (transposed): thread = column t, accumulates all 4 heads.
    {
        float a0 = 0.f, a1 = 0.f, a2 = 0.f, a3 = 0.f;
#pragma unroll
        for (int kk = 0; kk < 32; kk++) {
            float4 a4 = *(const float4*)(s_attnT + kk * 4);   // broadcast
            float pv = s_pair[kk * 128 + t];
            a0 += a4.x * pv; a1 += a4.y * pv; a2 += a4.z * pv; a3 += a4.w * pv;
        }
        st_hilo(g_Chi, g_Clo, cbase + 128 + 0 * 128 + t, a0);
        st_hilo(g_Chi, g_Clo, cbase + 128 + 1 * 128 + t, a1);
        st_hilo(g_Chi, g_Clo, cbase + 128 + 2 * 128 + t, a2);
        st_hilo(g_Chi, g_Clo, cbase + 128 + 3 * 128 + t, a3);
    }
    // pt sums: vp streamed from gmem
    if (t < 96) {
        int h = t / 24, j = t % 24;
        float acc = 0.f;
#pragma unroll
        for (int kk = 0; kk < 32; kk++)
            acc += s_attnT[kk * 4 + h] * __ldg(g_vp + (size_t)s_nb[kk] * 24 + j);
        s_pt[t] = acc;
    }
    if (t < 32) {  // zero K-padding 736..767
        g_Chi[cbase + 736 + t] = __float2bfloat16(0.f);
        g_Clo[cbase + 736 + t] = __float2bfloat16(0.f);
    }
    __syncthreads();
    if (t < 96) {
        int h = t / 24, pj = (t % 24) / 3, aidx = t % 3;
        const float* fr = frames + (size_t)n * 16;
        float r0 = fr[0 * 4 + aidx], r1 = fr[1 * 4 + aidx], r2 = fr[2 * 4 + aidx];
        float v0 = s_pt[h * 24 + pj * 3 + 0] - fr[0 * 4 + 3];
        float v1 = s_pt[h * 24 + pj * 3 + 1] - fr[1 * 4 + 3];
        float v2 = s_pt[h * 24 + pj * 3 + 2] - fr[2 * 4 + 3];
        st_hilo(g_Chi, g_Clo, cbase + 640 + t, r0 * v0 + r1 * v1 + r2 * v2);
    }
}

// ---------------- launch ----------------
extern "C" void kernel_launch(void* const* d_in, const int* in_sizes, int n_in,
                              void* d_out, int out_size)
{
    const float* local      = (const float*)d_in[0];
    const float* pair       = (const float*)d_in[1];
    const float* frames     = (const float*)d_in[2];
    const int*   neighbours = (const int*)  d_in[3];
    // d_in[4] = mask (all-true by construction; identity)
    const float* Wq  = (const float*)d_in[5];
    const float* bq  = (const float*)d_in[6];
    const float* Wk  = (const float*)d_in[7];
    const float* bk  = (const float*)d_in[8];
    const float* Wv  = (const float*)d_in[9];
    const float* bv  = (const float*)d_in[10];
    const float* Wqp = (const float*)d_in[11];
    const float* bqp = (const float*)d_in[12];
    const float* Wkp = (const float*)d_in[13];
    const float* bkp = (const float*)d_in[14];
    const float* Wvp = (const float*)d_in[15];
    const float* bvp = (const float*)d_in[16];
    const float* Wb  = (const float*)d_in[17];
    const float* gamma = (const float*)d_in[18];
    const float* Wout  = (const float*)d_in[19];
    float* out = (float*)d_out;

    void *p_Lhi, *p_Llo, *p_WpT_hi, *p_WpT_lo, *p_bias, *p_WoT_hi, *p_WoT_lo;
    void *p_Chi, *p_Clo, *p_proj;
    cudaGetSymbolAddress(&p_Lhi, g_Lhi);       cudaGetSymbolAddress(&p_Llo, g_Llo);
    cudaGetSymbolAddress(&p_WpT_hi, g_WpT_hi); cudaGetSymbolAddress(&p_WpT_lo, g_WpT_lo);
    cudaGetSymbolAddress(&p_bias, g_biasp);
    cudaGetSymbolAddress(&p_WoT_hi, g_WoT_hi); cudaGetSymbolAddress(&p_WoT_lo, g_WoT_lo);
    cudaGetSymbolAddress(&p_Chi, g_Chi);       cudaGetSymbolAddress(&p_Clo, g_Clo);
    cudaGetSymbolAddress(&p_proj, g_proj);

    cudaFuncSetAttribute(mma_gemm, cudaFuncAttributeMaxDynamicSharedMemorySize, STG2_BYTES);

    // 0) local hi/lo split + bias
    prep_local<<<2048, 256>>>(local, bq, bk, bv, bqp, bkp, bvp);

    // 1) Wproj transpose (coalesced tiles)
    prep_wpt<<<dim3(NPAD / 32, CLd / 32), dim3(32, 8)>>>(Wq, Wk, Wv, Wqp, Wkp, Wvp);

    // 2) Wout transpose (coalesced tiles)
    prep_wot<<<dim3(NPAD / 32, KP2 / 32), dim3(32, 8)>>>(Wout);

    // 3) proj = local @ Wproj + bias   (K=384)   <- profile capture slot
    mma_gemm<<<dim3(4, 64), 256, STG2_BYTES>>>(
        (const __nv_bfloat16*)p_Lhi, (const __nv_bfloat16*)p_Llo,
        (const __nv_bfloat16*)p_WpT_hi, (const __nv_bfloat16*)p_WpT_lo,
        (const float*)p_bias, (float*)p_proj, CLd);

    // 4) LN + frame transforms
    proj_epilogue<<<NN / 8, 256>>>(frames);

    // 5) attention -> bf16 hi/lo concat
    attn_kernel<<<NN, 128>>>(pair, neighbours, frames, Wb, gamma);

    // 6) out = concat @ Wout   (K=768)
    mma_gemm<<<dim3(4, 64), 256, STG2_BYTES>>>(
        (const __nv_bfloat16*)p_Chi, (const __nv_bfloat16*)p_Clo,
        (const __nv_bfloat16*)p_WoT_hi, (const __nv_bfloat16*)p_WoT_lo,
        nullptr, out, KP2);
}

// round 14
// speedup vs baseline: 1.1397x; 1.1397x over previous
#include <cuda_runtime.h>
#include <cuda_bf16.h>
#include <math.h>
#include <stdint.h>

// ---------------- problem constants ----------------
#define NN    8192
#define KNB   32
#define CLd   384
#define CPd   128
#define Hh    4
#define Sd    32
#define Pp    8
#define PROJ  336
#define NPAD  384
#define CONC  736
#define KP2   768

// ---------------- scratch (device globals; no allocation) ----------------
__device__ __align__(16) float g_Atf[NN * CLd];      // tf32-rounded local
__device__ __align__(16) float g_WpT[NPAD * CLd];    // tf32-rounded Wproj^T (padded)
__device__ __align__(16) float g_biasp[NPAD];
__device__ __align__(16) float g_WoT[NPAD * KP2];    // tf32-rounded Wout^T (padded)
__device__ __align__(16) float g_C[NN * KP2];        // tf32-rounded concat
__device__ __align__(16) float g_proj[NN * NPAD];
__device__ __align__(16) float g_q [NN * 128];
__device__ __align__(16) float g_k [NN * 32];
__device__ __align__(16) float g_v [NN * 32];
__device__ __align__(16) float g_qp[NN * 96];
__device__ __align__(16) float g_kp[NN * 24];
__device__ __align__(16) float g_vp[NN * 24];

// ---------------- PTX helpers ----------------
__device__ __forceinline__ uint32_t smem_u32(const void* p) {
    uint32_t a;
    asm("{ .reg .u64 t; cvta.to.shared.u64 t, %1; cvt.u32.u64 %0, t; }" : "=r"(a) : "l"(p));
    return a;
}
__device__ __forceinline__ float to_tf32(float x) {
    float r;
    asm("cvt.rna.tf32.f32 %0, %1;" : "=f"(r) : "f"(x));
    return r;
}

#define CP16(dst, src) \
    asm volatile("cp.async.cg.shared.global [%0], [%1], 16;" :: "r"(dst), "l"(src))
#define CP_COMMIT() asm volatile("cp.async.commit_group;" ::: "memory")
#define CP_WAIT(n)  asm volatile("cp.async.wait_group %0;" :: "n"(n) : "memory")

#define LDSM4(R, addr) \
    asm volatile("ldmatrix.sync.aligned.m8n8.x4.shared.b16 {%0,%1,%2,%3}, [%4];" \
        : "=r"((R)[0]), "=r"((R)[1]), "=r"((R)[2]), "=r"((R)[3]) : "r"(addr))

#define MMATF32(C, A, b0, b1) \
    asm volatile("mma.sync.aligned.m16n8k8.row.col.f32.tf32.tf32.f32 " \
        "{%0,%1,%2,%3}, {%4,%5,%6,%7}, {%8,%9}, {%0,%1,%2,%3};" \
        : "+f"((C)[0]), "+f"((C)[1]), "+f"((C)[2]), "+f"((C)[3]) \
        : "r"((A)[0]), "r"((A)[1]), "r"((A)[2]), "r"((A)[3]), "r"(b0), "r"(b1))

// ---------------- misc warp helpers ----------------
__device__ __forceinline__ float warp_sum(float v) {
#pragma unroll
    for (int o = 16; o; o >>= 1) v += __shfl_xor_sync(0xffffffffu, v, o);
    return v;
}
__device__ __forceinline__ float warp_max(float v) {
#pragma unroll
    for (int o = 16; o; o >>= 1) v = fmaxf(v, __shfl_xor_sync(0xffffffffu, v, o));
    return v;
}
__device__ __forceinline__ float2 warp_sum2(float a, float b) {
#pragma unroll
    for (int o = 16; o; o >>= 1) {
        a += __shfl_xor_sync(0xffffffffu, a, o);
        b += __shfl_xor_sync(0xffffffffu, b, o);
    }
    return make_float2(a, b);
}

// ---------------- prep kernel 1: local tf32 rounding + bias ----------------
__global__ void prep_local(
    const float* __restrict__ local,
    const float* __restrict__ bq,  const float* __restrict__ bk,
    const float* __restrict__ bv,  const float* __restrict__ bqp,
    const float* __restrict__ bkp, const float* __restrict__ bvp)
{
    const int total = NN * CLd;
    for (int idx = blockIdx.x * blockDim.x + threadIdx.x; idx < total;
         idx += gridDim.x * blockDim.x) {
        g_Atf[idx] = to_tf32(local[idx]);
    }
    int idx = blockIdx.x * blockDim.x + threadIdx.x;
    if (idx < NPAD) {
        int n = idx;
        float b = 0.f;
        if      (n < 128) b = bq [n];
        else if (n < 160) b = bk [n - 128];
        else if (n < 192) b = bv [n - 160];
        else if (n < 288) b = bqp[n - 192];
        else if (n < 312) b = bkp[n - 288];
        else if (n < 336) b = bvp[n - 312];
        g_biasp[n] = b;
    }
}

// ---------------- prep kernel 2: Wproj transpose (coalesced, tf32) ----------------
__global__ void __launch_bounds__(256) prep_wpt(
    const float* __restrict__ Wq,  const float* __restrict__ Wk,
    const float* __restrict__ Wv,  const float* __restrict__ Wqp,
    const float* __restrict__ Wkp, const float* __restrict__ Wvp)
{
    __shared__ float tile[32][33];
    const int n0 = blockIdx.x * 32, k0 = blockIdx.y * 32;
    const int tx = threadIdx.x, ty = threadIdx.y;
#pragma unroll
    for (int i = 0; i < 4; i++) {
        int k = k0 + ty + i * 8, n = n0 + tx;
        float w = 0.f;
        if      (n < 128) w = Wq [k * 128 + n];
        else if (n < 160) w = Wk [k * 32  + (n - 128)];
        else if (n < 192) w = Wv [k * 32  + (n - 160)];
        else if (n < 288) w = Wqp[k * 96  + (n - 192)];
        else if (n < 312) w = Wkp[k * 24  + (n - 288)];
        else if (n < 336) w = Wvp[k * 24  + (n - 312)];
        tile[ty + i * 8][tx] = w;
    }
    __syncthreads();
#pragma unroll
    for (int i = 0; i < 4; i++) {
        int n = n0 + ty + i * 8, k = k0 + tx;
        g_WpT[(size_t)n * CLd + k] = to_tf32(tile[tx][ty + i * 8]);
    }
}

// ---------------- prep kernel 3: Wout transpose (coalesced, tf32) ----------------
__global__ void __launch_bounds__(256) prep_wot(const float* __restrict__ Wout)
{
    __shared__ float tile[32][33];
    const int n0 = blockIdx.x * 32, k0 = blockIdx.y * 32;
    const int tx = threadIdx.x, ty = threadIdx.y;
#pragma unroll
    for (int i = 0; i < 4; i++) {
        int k = k0 + ty + i * 8, n = n0 + tx;
        float w = (k < CONC) ? Wout[(size_t)k * CLd + n] : 0.f;
        tile[ty + i * 8][tx] = w;
    }
    __syncthreads();
#pragma unroll
    for (int i = 0; i < 4; i++) {
        int n = n0 + ty + i * 8, k = k0 + tx;
        g_WoT[(size_t)n * KP2 + k] = to_tf32(tile[tx][ty + i * 8]);
    }
}

// ---------------- tf32 HMMA GEMM: C[8192,384] = A @ B^T ----------------
// BM=128, BN=192, BK=32 (tf32), 512 threads (4m x 4n warps, 32x48 warp tile),
// double-buffered. Stage: A 128x144B = 18432, B 192x144B = 27648 -> 46080/stage.
#define TSTG_BYTES 46080
#define TOFF_B 18432
#define TGEMM_SMEM (2 * TSTG_BYTES)

__device__ __forceinline__ void issue_tile_f32(uint32_t sdst, const float* __restrict__ src,
                                               int K, int kk, int tid, int nchunks)
{
#pragma unroll
    for (int i = tid; i < nchunks; i += 512) {
        int r = i >> 3, c = i & 7;   // row, 16B chunk (4 floats)
        CP16(sdst + r * 144 + c * 16, src + (size_t)r * K + kk + c * 4);
    }
}

__global__ void __launch_bounds__(512, 1) mma_gemm(
    const float* __restrict__ A,   // [M, K] row-major (tf32-rounded fp32)
    const float* __restrict__ B,   // [384, K] row-major (tf32-rounded fp32)
    const float* __restrict__ bias, float* __restrict__ C, int K)
{
    extern __shared__ char dsm[];
    const uint32_t sbase = smem_u32(dsm);
    const int tid  = threadIdx.x;
    const int lane = tid & 31;
    const int wid  = tid >> 5;
    const int wm   = wid >> 2;          // 0..3
    const int wn   = wid & 3;           // 0..3
    const int rowBase = blockIdx.y * 128;
    const int colBase = blockIdx.x * 192;
    const int NC = K >> 5;              // K/32 chunks

    const float* pA = A + (size_t)rowBase * K;
    const float* pB = B + (size_t)colBase * K;

    // A frag addresses: 16 rows x k8 (32B): lane -> row (lane&15), k-half (lane>>4)*16B
    const uint32_t aoff = (uint32_t)((lane & 15) * 144 + ((lane >> 4) << 4));
    // B frag addresses: x4 covers 2 n-tiles x k8: row (lane>>4)*8+(lane&7), k-half ((lane>>3)&1)*16B
    const uint32_t boff = (uint32_t)((((lane >> 4) * 8 + (lane & 7)) * 144) + (((lane >> 3) & 1) << 4));
    const uint32_t awbase = (uint32_t)(wm * 32 * 144);
    const uint32_t bwbase = (uint32_t)(wn * 48 * 144);

    float acc[2][6][4];
#pragma unroll
    for (int i = 0; i < 2; i++)
#pragma unroll
        for (int j = 0; j < 6; j++)
#pragma unroll
            for (int q = 0; q < 4; q++) acc[i][j][q] = 0.f;

    // prefetch chunk 0
    issue_tile_f32(sbase,          pA, K, 0, tid, 1024);
    issue_tile_f32(sbase + TOFF_B, pB, K, 0, tid, 1536);
    CP_COMMIT();

    for (int i = 0; i < NC; i++) {
        if (i + 1 < NC) {
            uint32_t st = sbase + (uint32_t)((i + 1) & 1) * TSTG_BYTES;
            int kk = (i + 1) << 5;
            issue_tile_f32(st,          pA, K, kk, tid, 1024);
            issue_tile_f32(st + TOFF_B, pB, K, kk, tid, 1536);
            CP_COMMIT();
            CP_WAIT(1);
        } else {
            CP_WAIT(0);
        }
        __syncthreads();

        const uint32_t st = sbase + (uint32_t)(i & 1) * TSTG_BYTES;
        const uint32_t sA = st + awbase;
        const uint32_t sB = st + TOFF_B + bwbase;

#pragma unroll
        for (int s = 0; s < 4; s++) {            // 4 k8-steps per 32-K chunk
            const uint32_t ka = (uint32_t)(s * 32);   // 8 tf32 = 32 bytes
            uint32_t av[8], bv[12];
            LDSM4(av,     sA + ka + aoff);            // rows wm*32..+15
            LDSM4(av + 4, sA + 16 * 144 + ka + aoff); // rows +16..31
#pragma unroll
            for (int L = 0; L < 3; L++)
                LDSM4(bv + L * 4, sB + (uint32_t)(L * 16 * 144) + ka + boff);
#pragma unroll
            for (int mf = 0; mf < 2; mf++) {
#pragma unroll
                for (int nt = 0; nt < 6; nt++) {
                    const int L = nt >> 1, h = (nt & 1) * 2;
                    MMATF32(acc[mf][nt], av + mf * 4, bv[L * 4 + h], bv[L * 4 + h + 1]);
                }
            }
        }
        __syncthreads();
    }

    const int r0 = lane >> 2;
    const int c0 = (lane & 3) * 2;
#pragma unroll
    for (int mf = 0; mf < 2; mf++) {
#pragma unroll
        for (int nt = 0; nt < 6; nt++) {
            int row = rowBase + wm * 32 + mf * 16 + r0;
            int col = colBase + wn * 48 + nt * 8 + c0;
            float b0 = 0.f, b1 = 0.f;
            if (bias) { b0 = bias[col]; b1 = bias[col + 1]; }
            float2 v0 = make_float2(acc[mf][nt][0] + b0, acc[mf][nt][1] + b1);
            float2 v1 = make_float2(acc[mf][nt][2] + b0, acc[mf][nt][3] + b1);
            *(float2*)(C + (size_t)row * NPAD + col)       = v0;
            *(float2*)(C + (size_t)(row + 8) * NPAD + col) = v1;
        }
    }
}

// ---------------- kernel: LN + frame transforms ----------------
__global__ void __launch_bounds__(256) proj_epilogue(const float* __restrict__ frames)
{
    const int warp = threadIdx.x >> 5;
    const int lane = threadIdx.x & 31;
    const int n = blockIdx.x * 8 + warp;
    if (n >= NN) return;
    const float* pr = g_proj + (size_t)n * NPAD;
    const float inv_sqrtS = 0.17677669529663687f;

#pragma unroll
    for (int h = 0; h < Hh; h++) {
        float x  = pr[h * 32 + lane];
        float2 s = warp_sum2(x, x * x);
        float mu = s.x * (1.f / 32.f);
        float var = s.y * (1.f / 32.f) - mu * mu;
        g_q[(size_t)n * 128 + h * 32 + lane] = (x - mu) * rsqrtf(var + 1e-5f) * inv_sqrtS;
    }
    {
        float x  = pr[128 + lane];
        float2 s = warp_sum2(x, x * x);
        float mu = s.x * (1.f / 32.f);
        float var = s.y * (1.f / 32.f) - mu * mu;
        g_k[(size_t)n * 32 + lane] = (x - mu) * rsqrtf(var + 1e-5f);
    }
    g_v[(size_t)n * 32 + lane] = pr[160 + lane];

    const float* fr = frames + (size_t)n * 16;
    float R00 = fr[0],  R01 = fr[1],  R02 = fr[2],  t0 = fr[3];
    float R10 = fr[4],  R11 = fr[5],  R12 = fr[6],  t1 = fr[7];
    float R20 = fr[8],  R21 = fr[9],  R22 = fr[10], t2 = fr[11];

    {
        float px = pr[192 + lane * 3 + 0];
        float py = pr[192 + lane * 3 + 1];
        float pz = pr[192 + lane * 3 + 2];
        float* q = g_qp + (size_t)n * 96 + lane * 3;
        q[0] = R00 * px + R01 * py + R02 * pz + t0;
        q[1] = R10 * px + R11 * py + R12 * pz + t1;
        q[2] = R20 * px + R21 * py + R22 * pz + t2;
    }
    if (lane < 8) {
        float px = pr[288 + lane * 3 + 0];
        float py = pr[288 + lane * 3 + 1];
        float pz = pr[288 + lane * 3 + 2];
        float* q = g_kp + (size_t)n * 24 + lane * 3;
        q[0] = R00 * px + R01 * py + R02 * pz + t0;
        q[1] = R10 * px + R11 * py + R12 * pz + t1;
        q[2] = R20 * px + R21 * py + R22 * pz + t2;
    } else if (lane < 16) {
        int l2 = lane - 8;
        float px = pr[312 + l2 * 3 + 0];
        float py = pr[312 + l2 * 3 + 1];
        float pz = pr[312 + l2 * 3 + 2];
        float* q = g_vp + (size_t)n * 24 + l2 * 3;
        q[0] = R00 * px + R01 * py + R02 * pz + t0;
        q[1] = R10 * px + R11 * py + R12 * pz + t1;
        q[2] = R20 * px + R21 * py + R22 * pz + t2;
    }
}

// ---------------- kernel: attention (R9 structure; single tf32 fp32 output) ----------------
__global__ void __launch_bounds__(128, 8) attn_kernel(
    const float* __restrict__ pair,        // N*K*CP
    const int*   __restrict__ neighbours,  // N*K
    const float* __restrict__ frames,      // N*16
    const float* __restrict__ Wb,          // CP*H
    const float* __restrict__ gamma)       // H
{
    const int n    = blockIdx.x;
    const int t    = threadIdx.x;
    const int lane = t & 31;
    const int warp = t >> 5;

    __shared__ float s_q[128];
    __shared__ float s_qp[96];
    __shared__ int   s_nb[32];
    __shared__ float s_k [32][33];
    __shared__ float s_kp[32][25];
    __shared__ __align__(16) float s_pair[32 * 128];
    __shared__ __align__(16) float s_WbT[4 * 128];
    __shared__ __align__(16) float s_pb2[2 * 128];    // [half][k*4+h]
    __shared__ __align__(16) float s_attnT[32 * 4];   // [k][h]
    __shared__ float s_pt[96];

    // async pair load (16KB) — overlaps gathers
    {
        const uint32_t sp = smem_u32(s_pair);
        const float* psrc = pair + (size_t)n * 4096;
#pragma unroll
        for (int j = 0; j < 8; j++) {
            int i = t + 128 * j;
            CP16(sp + (uint32_t)i * 16, psrc + i * 4);
        }
        CP_COMMIT();
    }

    if (t < 32) s_nb[t] = neighbours[(size_t)n * 32 + t];
    s_q[t] = g_q[(size_t)n * 128 + t];
    if (t < 96) s_qp[t] = g_qp[(size_t)n * 96 + t];
    for (int i = t; i < 512; i += 128) {
        int c = i & 127, h = i >> 7;
        s_WbT[h * 128 + c] = Wb[c * 4 + h];
    }
    __syncthreads();   // s_nb ready

    // k gather
#pragma unroll
    for (int i = t; i < 256; i += 128) {
        int row = i >> 3, c4 = i & 7, nb = s_nb[row];
        float4 kv = *(const float4*)(g_k + (size_t)nb * 32 + c4 * 4);
        s_k[row][c4*4+0]=kv.x; s_k[row][c4*4+1]=kv.y; s_k[row][c4*4+2]=kv.z; s_k[row][c4*4+3]=kv.w;
    }
    // kp gather
#pragma unroll
    for (int i = t; i < 192; i += 128) {
        int row = i / 6, c4 = i % 6, nb = s_nb[row];
        float4 a4 = *(const float4*)(g_kp + (size_t)nb * 24 + c4 * 4);
        s_kp[row][c4*4+0]=a4.x; s_kp[row][c4*4+1]=a4.y; s_kp[row][c4*4+2]=a4.z; s_kp[row][c4*4+3]=a4.w;
    }
    CP_WAIT(0);
    __syncthreads();

    // pb partials: warp w -> heads {h0, h0+1}, column half [64*(w&1), +64).
    {
        const int half = warp & 1;
        const int h0   = (warp >> 1) << 1;
        const float4* prow = (const float4*)(s_pair + lane * 128 + half * 64);
        const float4* wr0  = (const float4*)(s_WbT + (h0 + 0) * 128 + half * 64);
        const float4* wr1  = (const float4*)(s_WbT + (h0 + 1) * 128 + half * 64);
        float pp0 = 0.f, pp1 = 0.f;
#pragma unroll
        for (int i = 0; i < 16; i++) {
            int c4 = (i + lane) & 15;
            float4 p  = prow[c4];
            float4 wa = wr0[c4];
            float4 wb = wr1[c4];
            pp0 += p.x * wa.x + p.y * wa.y + p.z * wa.z + p.w * wa.w;
            pp1 += p.x * wb.x + p.y * wb.y + p.z * wb.z + p.w * wb.w;
        }
        *(float2*)(s_pb2 + half * 128 + lane * 4 + h0) = make_float2(pp0, pp1);
    }
    __syncthreads();

    // ---- logits: head = warp, neighbour = lane ----
    const float w_L = 0.5773502691896258f;
    float gam   = gamma[warp];
    float scale = log1pf(__expf(gam)) * (1.0f / 6.0f) * 0.5f;

    float qk = 0.f;
#pragma unroll
    for (int s = 0; s < 32; s++) qk += s_q[warp * 32 + s] * s_k[lane][s];

    float dist = 0.f;
#pragma unroll
    for (int p = 0; p < 8; p++) {
        float dx = s_qp[warp * 24 + p * 3 + 0] - s_kp[lane][p * 3 + 0];
        float dy = s_qp[warp * 24 + p * 3 + 1] - s_kp[lane][p * 3 + 1];
        float dz = s_qp[warp * 24 + p * 3 + 2] - s_kp[lane][p * 3 + 2];
        dist += dx * dx + dy * dy + dz * dz;
    }

    float pb = s_pb2[lane * 4 + warp] + s_pb2[128 + lane * 4 + warp];

    float logit = w_L * (qk - scale * dist + pb);
    float m = warp_max(logit);
    float e = __expf(logit - m);
    float sm = warp_sum(e);
    s_attnT[lane * 4 + warp] = e / sm;    // [k][h]
    __syncthreads();

    float* conc = g_C + (size_t)n * KP2;

    // local_up
    {
        float acc = 0.f;
#pragma unroll
        for (int kk = 0; kk < 32; kk++)
            acc += s_attnT[kk * 4 + warp] * __ldg(g_v + (size_t)s_nb[kk] * 32 + lane);
        conc[warp * 32 + lane] = to_tf32(acc);
    }
    // pair_up (transposed): thread = column t, 4 heads
    {
        float a0 = 0.f, a1 = 0.f, a2 = 0.f, a3 = 0.f;
#pragma unroll
        for (int kk = 0; kk < 32; kk++) {
            float4 a4 = *(const float4*)(s_attnT + kk * 4);   // broadcast
            float pv = s_pair[kk * 128 + t];
            a0 += a4.x * pv; a1 += a4.y * pv; a2 += a4.z * pv; a3 += a4.w * pv;
        }
        conc[128 + 0 * 128 + t] = to_tf32(a0);
        conc[128 + 1 * 128 + t] = to_tf32(a1);
        conc[128 + 2 * 128 + t] = to_tf32(a2);
        conc[128 + 3 * 128 + t] = to_tf32(a3);
    }
    // pt sums
    if (t < 96) {
        int h = t / 24, j = t % 24;
        float acc = 0.f;
#pragma unroll
        for (int kk = 0; kk < 32; kk++)
            acc += s_attnT[kk * 4 + h] * __ldg(g_vp + (size_t)s_nb[kk] * 24 + j);
        s_pt[t] = acc;
    }
    if (t < 32) conc[736 + t] = 0.f;   // zero K-padding
    __syncthreads();
    if (t < 96) {
        int h = t / 24, pj = (t % 24) / 3, aidx = t % 3;
        const float* fr = frames + (size_t)n * 16;
        float r0 = fr[0 * 4 + aidx], r1 = fr[1 * 4 + aidx], r2 = fr[2 * 4 + aidx];
        float v0 = s_pt[h * 24 + pj * 3 + 0] - fr[0 * 4 + 3];
        float v1 = s_pt[h * 24 + pj * 3 + 1] - fr[1 * 4 + 3];
        float v2 = s_pt[h * 24 + pj * 3 + 2] - fr[2 * 4 + 3];
        conc[640 + t] = to_tf32(r0 * v0 + r1 * v1 + r2 * v2);
    }
}

// ---------------- launch ----------------
extern "C" void kernel_launch(void* const* d_in, const int* in_sizes, int n_in,
                              void* d_out, int out_size)
{
    const float* local      = (const float*)d_in[0];
    const float* pair       = (const float*)d_in[1];
    const float* frames     = (const float*)d_in[2];
    const int*   neighbours = (const int*)  d_in[3];
    // d_in[4] = mask (all-true by construction; identity)
    const float* Wq  = (const float*)d_in[5];
    const float* bq  = (const float*)d_in[6];
    const float* Wk  = (const float*)d_in[7];
    const float* bk  = (const float*)d_in[8];
    const float* Wv  = (const float*)d_in[9];
    const float* bv  = (const float*)d_in[10];
    const float* Wqp = (const float*)d_in[11];
    const float* bqp = (const float*)d_in[12];
    const float* Wkp = (const float*)d_in[13];
    const float* bkp = (const float*)d_in[14];
    const float* Wvp = (const float*)d_in[15];
    const float* bvp = (const float*)d_in[16];
    const float* Wb  = (const float*)d_in[17];
    const float* gamma = (const float*)d_in[18];
    const float* Wout  = (const float*)d_in[19];
    float* out = (float*)d_out;

    void *p_Atf, *p_WpT, *p_bias, *p_WoT, *p_C, *p_proj;
    cudaGetSymbolAddress(&p_Atf, g_Atf);
    cudaGetSymbolAddress(&p_WpT, g_WpT);
    cudaGetSymbolAddress(&p_bias, g_biasp);
    cudaGetSymbolAddress(&p_WoT, g_WoT);
    cudaGetSymbolAddress(&p_C, g_C);
    cudaGetSymbolAddress(&p_proj, g_proj);

    cudaFuncSetAttribute(mma_gemm, cudaFuncAttributeMaxDynamicSharedMemorySize, TGEMM_SMEM);

    // 0) local tf32 rounding + bias
    prep_local<<<2048, 256>>>(local, bq, bk, bv, bqp, bkp, bvp);

    // 1) Wproj transpose (coalesced tiles, tf32)
    prep_wpt<<<dim3(NPAD / 32, CLd / 32), dim3(32, 8)>>>(Wq, Wk, Wv, Wqp, Wkp, Wvp);

    // 2) Wout transpose (coalesced tiles, tf32)
    prep_wot<<<dim3(NPAD / 32, KP2 / 32), dim3(32, 8)>>>(Wout);

    // 3) proj = local @ Wproj + bias   (K=384)   <- profile capture slot
    mma_gemm<<<dim3(2, 64), 512, TGEMM_SMEM>>>(
        (const float*)p_Atf, (const float*)p_WpT,
        (const float*)p_bias, (float*)p_proj, CLd);

    // 4) LN + frame transforms
    proj_epilogue<<<NN / 8, 256>>>(frames);

    // 5) attention -> tf32 concat
    attn_kernel<<<NN, 128>>>(pair, neighbours, frames, Wb, gamma);

    // 6) out = concat @ Wout   (K=768)
    mma_gemm<<<dim3(2, 64), 512, TGEMM_SMEM>>>(
        (const float*)p_C, (const float*)p_WoT,
        nullptr, out, KP2);
}

// round 15
// speedup vs baseline: 1.1696x; 1.0262x over previous
#include <cuda_runtime.h>
#include <cuda_bf16.h>
#include <math.h>
#include <stdint.h>

// ---------------- problem constants ----------------
#define NN    8192
#define KNB   32
#define CLd   384
#define CPd   128
#define Hh    4
#define Sd    32
#define Pp    8
#define PROJ  336
#define NPAD  384
#define CONC  736
#define KP2   768

// ---------------- scratch (device globals; no allocation) ----------------
__device__ __align__(16) float g_Atf[NN * CLd];      // tf32-rounded local
__device__ __align__(16) float g_WpT[NPAD * CLd];    // tf32-rounded Wproj^T (padded)
__device__ __align__(16) float g_biasp[NPAD];
__device__ __align__(16) float g_WoT[NPAD * KP2];    // tf32-rounded Wout^T (padded)
__device__ __align__(16) float g_C[NN * KP2];        // tf32-rounded concat
__device__ __align__(16) float g_proj[NN * NPAD];
__device__ __align__(16) float g_q [NN * 128];
__device__ __align__(16) float g_k [NN * 32];
__device__ __align__(16) float g_v [NN * 32];
__device__ __align__(16) float g_qp[NN * 96];
__device__ __align__(16) float g_kp[NN * 24];
__device__ __align__(16) float g_vp[NN * 24];

// ---------------- PTX helpers ----------------
__device__ __forceinline__ uint32_t smem_u32(const void* p) {
    uint32_t a;
    asm("{ .reg .u64 t; cvta.to.shared.u64 t, %1; cvt.u32.u64 %0, t; }" : "=r"(a) : "l"(p));
    return a;
}
__device__ __forceinline__ float to_tf32(float x) {
    float r;
    asm("cvt.rna.tf32.f32 %0, %1;" : "=f"(r) : "f"(x));
    return r;
}

#define CP16(dst, src) \
    asm volatile("cp.async.cg.shared.global [%0], [%1], 16;" :: "r"(dst), "l"(src))
#define CP_COMMIT() asm volatile("cp.async.commit_group;" ::: "memory")
#define CP_WAIT(n)  asm volatile("cp.async.wait_group %0;" :: "n"(n) : "memory")

#define LDSM4(R, addr) \
    asm volatile("ldmatrix.sync.aligned.m8n8.x4.shared.b16 {%0,%1,%2,%3}, [%4];" \
        : "=r"((R)[0]), "=r"((R)[1]), "=r"((R)[2]), "=r"((R)[3]) : "r"(addr))

#define MMATF32(C, A, b0, b1) \
    asm volatile("mma.sync.aligned.m16n8k8.row.col.f32.tf32.tf32.f32 " \
        "{%0,%1,%2,%3}, {%4,%5,%6,%7}, {%8,%9}, {%0,%1,%2,%3};" \
        : "+f"((C)[0]), "+f"((C)[1]), "+f"((C)[2]), "+f"((C)[3]) \
        : "r"((A)[0]), "r"((A)[1]), "r"((A)[2]), "r"((A)[3]), "r"(b0), "r"(b1))

// ---------------- misc warp helpers ----------------
__device__ __forceinline__ float warp_sum(float v) {
#pragma unroll
    for (int o = 16; o; o >>= 1) v += __shfl_xor_sync(0xffffffffu, v, o);
    return v;
}
__device__ __forceinline__ float warp_max(float v) {
#pragma unroll
    for (int o = 16; o; o >>= 1) v = fmaxf(v, __shfl_xor_sync(0xffffffffu, v, o));
    return v;
}
__device__ __forceinline__ float2 warp_sum2(float a, float b) {
#pragma unroll
    for (int o = 16; o; o >>= 1) {
        a += __shfl_xor_sync(0xffffffffu, a, o);
        b += __shfl_xor_sync(0xffffffffu, b, o);
    }
    return make_float2(a, b);
}

// ---------------- prep kernel 1: local tf32 rounding + bias ----------------
__global__ void prep_local(
    const float* __restrict__ local,
    const float* __restrict__ bq,  const float* __restrict__ bk,
    const float* __restrict__ bv,  const float* __restrict__ bqp,
    const float* __restrict__ bkp, const float* __restrict__ bvp)
{
    const int total = NN * CLd;
    for (int idx = blockIdx.x * blockDim.x + threadIdx.x; idx < total;
         idx += gridDim.x * blockDim.x) {
        g_Atf[idx] = to_tf32(local[idx]);
    }
    int idx = blockIdx.x * blockDim.x + threadIdx.x;
    if (idx < NPAD) {
        int n = idx;
        float b = 0.f;
        if      (n < 128) b = bq [n];
        else if (n < 160) b = bk [n - 128];
        else if (n < 192) b = bv [n - 160];
        else if (n < 288) b = bqp[n - 192];
        else if (n < 312) b = bkp[n - 288];
        else if (n < 336) b = bvp[n - 312];
        g_biasp[n] = b;
    }
}

// ---------------- prep kernel 2: Wproj transpose (coalesced, tf32) ----------------
__global__ void __launch_bounds__(256) prep_wpt(
    const float* __restrict__ Wq,  const float* __restrict__ Wk,
    const float* __restrict__ Wv,  const float* __restrict__ Wqp,
    const float* __restrict__ Wkp, const float* __restrict__ Wvp)
{
    __shared__ float tile[32][33];
    const int n0 = blockIdx.x * 32, k0 = blockIdx.y * 32;
    const int tx = threadIdx.x, ty = threadIdx.y;
#pragma unroll
    for (int i = 0; i < 4; i++) {
        int k = k0 + ty + i * 8, n = n0 + tx;
        float w = 0.f;
        if      (n < 128) w = Wq [k * 128 + n];
        else if (n < 160) w = Wk [k * 32  + (n - 128)];
        else if (n < 192) w = Wv [k * 32  + (n - 160)];
        else if (n < 288) w = Wqp[k * 96  + (n - 192)];
        else if (n < 312) w = Wkp[k * 24  + (n - 288)];
        else if (n < 336) w = Wvp[k * 24  + (n - 312)];
        tile[ty + i * 8][tx] = w;
    }
    __syncthreads();
#pragma unroll
    for (int i = 0; i < 4; i++) {
        int n = n0 + ty + i * 8, k = k0 + tx;
        g_WpT[(size_t)n * CLd + k] = to_tf32(tile[tx][ty + i * 8]);
    }
}

// ---------------- prep kernel 3: Wout transpose (coalesced, tf32) ----------------
__global__ void __launch_bounds__(256) prep_wot(const float* __restrict__ Wout)
{
    __shared__ float tile[32][33];
    const int n0 = blockIdx.x * 32, k0 = blockIdx.y * 32;
    const int tx = threadIdx.x, ty = threadIdx.y;
#pragma unroll
    for (int i = 0; i < 4; i++) {
        int k = k0 + ty + i * 8, n = n0 + tx;
        float w = (k < CONC) ? Wout[(size_t)k * CLd + n] : 0.f;
        tile[ty + i * 8][tx] = w;
    }
    __syncthreads();
#pragma unroll
    for (int i = 0; i < 4; i++) {
        int n = n0 + ty + i * 8, k = k0 + tx;
        g_WoT[(size_t)n * KP2 + k] = to_tf32(tile[tx][ty + i * 8]);
    }
}

// ---------------- tf32 HMMA GEMM: C[8192,384] = A @ B^T ----------------
// BM=128, BN=192, BK=64 (tf32), 512 threads (4m x 4n warps, 32x48 warp tile),
// double-buffered. Row stride 64 tf32 = 256B + 16 pad = 272B.
// Stage: A 128x272 = 34816, B 192x272 = 52224 -> 87040/stage; 2 stages = 174080.
#define TSTG_BYTES 87040
#define TOFF_B 34816
#define TGEMM_SMEM (2 * TSTG_BYTES)

__device__ __forceinline__ void issue_tile_f32(uint32_t sdst, const float* __restrict__ src,
                                               int K, int kk, int tid, int nchunks)
{
#pragma unroll
    for (int i = tid; i < nchunks; i += 512) {
        int r = i >> 4, c = i & 15;   // row, 16B chunk (4 floats), 16 chunks/row
        CP16(sdst + r * 272 + c * 16, src + (size_t)r * K + kk + c * 4);
    }
}

__global__ void __launch_bounds__(512, 1) mma_gemm(
    const float* __restrict__ A,   // [M, K] row-major (tf32-rounded fp32)
    const float* __restrict__ B,   // [384, K] row-major (tf32-rounded fp32)
    const float* __restrict__ bias, float* __restrict__ C, int K)
{
    extern __shared__ char dsm[];
    const uint32_t sbase = smem_u32(dsm);
    const int tid  = threadIdx.x;
    const int lane = tid & 31;
    const int wid  = tid >> 5;
    const int wm   = wid >> 2;          // 0..3
    const int wn   = wid & 3;           // 0..3
    const int rowBase = blockIdx.y * 128;
    const int colBase = blockIdx.x * 192;
    const int NC = K >> 6;              // K/64 chunks

    const float* pA = A + (size_t)rowBase * K;
    const float* pB = B + (size_t)colBase * K;

    const uint32_t aoff = (uint32_t)((lane & 15) * 272 + ((lane >> 4) << 4));
    const uint32_t boff = (uint32_t)((((lane >> 4) * 8 + (lane & 7)) * 272) + (((lane >> 3) & 1) << 4));
    const uint32_t awbase = (uint32_t)(wm * 32 * 272);
    const uint32_t bwbase = (uint32_t)(wn * 48 * 272);

    float acc[2][6][4];
#pragma unroll
    for (int i = 0; i < 2; i++)
#pragma unroll
        for (int j = 0; j < 6; j++)
#pragma unroll
            for (int q = 0; q < 4; q++) acc[i][j][q] = 0.f;

    // prefetch chunk 0
    issue_tile_f32(sbase,          pA, K, 0, tid, 2048);
    issue_tile_f32(sbase + TOFF_B, pB, K, 0, tid, 3072);
    CP_COMMIT();

    for (int i = 0; i < NC; i++) {
        if (i + 1 < NC) {
            uint32_t st = sbase + (uint32_t)((i + 1) & 1) * TSTG_BYTES;
            int kk = (i + 1) << 6;
            issue_tile_f32(st,          pA, K, kk, tid, 2048);
            issue_tile_f32(st + TOFF_B, pB, K, kk, tid, 3072);
            CP_COMMIT();
            CP_WAIT(1);
        } else {
            CP_WAIT(0);
        }
        __syncthreads();

        const uint32_t st = sbase + (uint32_t)(i & 1) * TSTG_BYTES;
        const uint32_t sA = st + awbase;
        const uint32_t sB = st + TOFF_B + bwbase;

#pragma unroll
        for (int s = 0; s < 8; s++) {            // 8 k8-steps per 64-K chunk
            const uint32_t ka = (uint32_t)(s * 32);   // 8 tf32 = 32 bytes
            uint32_t av[8], bv[12];
            LDSM4(av,     sA + ka + aoff);
            LDSM4(av + 4, sA + 16 * 272 + ka + aoff);
#pragma unroll
            for (int L = 0; L < 3; L++)
                LDSM4(bv + L * 4, sB + (uint32_t)(L * 16 * 272) + ka + boff);
#pragma unroll
            for (int mf = 0; mf < 2; mf++) {
#pragma unroll
                for (int nt = 0; nt < 6; nt++) {
                    const int L = nt >> 1, h = (nt & 1) * 2;
                    MMATF32(acc[mf][nt], av + mf * 4, bv[L * 4 + h], bv[L * 4 + h + 1]);
                }
            }
        }
        __syncthreads();
    }

    const int r0 = lane >> 2;
    const int c0 = (lane & 3) * 2;
#pragma unroll
    for (int mf = 0; mf < 2; mf++) {
#pragma unroll
        for (int nt = 0; nt < 6; nt++) {
            int row = rowBase + wm * 32 + mf * 16 + r0;
            int col = colBase + wn * 48 + nt * 8 + c0;
            float b0 = 0.f, b1 = 0.f;
            if (bias) { b0 = bias[col]; b1 = bias[col + 1]; }
            float2 v0 = make_float2(acc[mf][nt][0] + b0, acc[mf][nt][1] + b1);
            float2 v1 = make_float2(acc[mf][nt][2] + b0, acc[mf][nt][3] + b1);
            *(float2*)(C + (size_t)row * NPAD + col)       = v0;
            *(float2*)(C + (size_t)(row + 8) * NPAD + col) = v1;
        }
    }
}

// ---------------- kernel: LN + frame transforms ----------------
__global__ void __launch_bounds__(256) proj_epilogue(const float* __restrict__ frames)
{
    const int warp = threadIdx.x >> 5;
    const int lane = threadIdx.x & 31;
    const int n = blockIdx.x * 8 + warp;
    if (n >= NN) return;
    const float* pr = g_proj + (size_t)n * NPAD;
    const float inv_sqrtS = 0.17677669529663687f;

#pragma unroll
    for (int h = 0; h < Hh; h++) {
        float x  = pr[h * 32 + lane];
        float2 s = warp_sum2(x, x * x);
        float mu = s.x * (1.f / 32.f);
        float var = s.y * (1.f / 32.f) - mu * mu;
        g_q[(size_t)n * 128 + h * 32 + lane] = (x - mu) * rsqrtf(var + 1e-5f) * inv_sqrtS;
    }
    {
        float x  = pr[128 + lane];
        float2 s = warp_sum2(x, x * x);
        float mu = s.x * (1.f / 32.f);
        float var = s.y * (1.f / 32.f) - mu * mu;
        g_k[(size_t)n * 32 + lane] = (x - mu) * rsqrtf(var + 1e-5f);
    }
    g_v[(size_t)n * 32 + lane] = pr[160 + lane];

    const float* fr = frames + (size_t)n * 16;
    float R00 = fr[0],  R01 = fr[1],  R02 = fr[2],  t0 = fr[3];
    float R10 = fr[4],  R11 = fr[5],  R12 = fr[6],  t1 = fr[7];
    float R20 = fr[8],  R21 = fr[9],  R22 = fr[10], t2 = fr[11];

    {
        float px = pr[192 + lane * 3 + 0];
        float py = pr[192 + lane * 3 + 1];
        float pz = pr[192 + lane * 3 + 2];
        float* q = g_qp + (size_t)n * 96 + lane * 3;
        q[0] = R00 * px + R01 * py + R02 * pz + t0;
        q[1] = R10 * px + R11 * py + R12 * pz + t1;
        q[2] = R20 * px + R21 * py + R22 * pz + t2;
    }
    if (lane < 8) {
        float px = pr[288 + lane * 3 + 0];
        float py = pr[288 + lane * 3 + 1];
        float pz = pr[288 + lane * 3 + 2];
        float* q = g_kp + (size_t)n * 24 + lane * 3;
        q[0] = R00 * px + R01 * py + R02 * pz + t0;
        q[1] = R10 * px + R11 * py + R12 * pz + t1;
        q[2] = R20 * px + R21 * py + R22 * pz + t2;
    } else if (lane < 16) {
        int l2 = lane - 8;
        float px = pr[312 + l2 * 3 + 0];
        float py = pr[312 + l2 * 3 + 1];
        float pz = pr[312 + l2 * 3 + 2];
        float* q = g_vp + (size_t)n * 24 + l2 * 3;
        q[0] = R00 * px + R01 * py + R02 * pz + t0;
        q[1] = R10 * px + R11 * py + R12 * pz + t1;
        q[2] = R20 * px + R21 * py + R22 * pz + t2;
    }
}

// ---------------- kernel: attention (R14 + qk float4 ONLY; cap (128,7)) ----------------
__global__ void __launch_bounds__(128, 7) attn_kernel(
    const float* __restrict__ pair,        // N*K*CP
    const int*   __restrict__ neighbours,  // N*K
    const float* __restrict__ frames,      // N*16
    const float* __restrict__ Wb,          // CP*H
    const float* __restrict__ gamma)       // H
{
    const int n    = blockIdx.x;
    const int t    = threadIdx.x;
    const int lane = t & 31;
    const int warp = t >> 5;

    __shared__ __align__(16) float s_q[128];
    __shared__ float s_qp[96];
    __shared__ int   s_nb[32];
    __shared__ __align__(16) float s_k [32][36];   // stride 36: float4-friendly, conflict-free
    __shared__ float s_kp[32][25];
    __shared__ __align__(16) float s_pair[32 * 128];
    __shared__ __align__(16) float s_WbT[4 * 128];
    __shared__ __align__(16) float s_pb2[2 * 128];    // [half][k*4+h]
    __shared__ __align__(16) float s_attnT[32 * 4];   // [k][h]
    __shared__ float s_pt[96];

    // async pair load (16KB) — overlaps gathers
    {
        const uint32_t sp = smem_u32(s_pair);
        const float* psrc = pair + (size_t)n * 4096;
#pragma unroll
        for (int j = 0; j < 8; j++) {
            int i = t + 128 * j;
            CP16(sp + (uint32_t)i * 16, psrc + i * 4);
        }
        CP_COMMIT();
    }

    if (t < 32) s_nb[t] = neighbours[(size_t)n * 32 + t];
    s_q[t] = g_q[(size_t)n * 128 + t];
    if (t < 96) s_qp[t] = g_qp[(size_t)n * 96 + t];
    for (int i = t; i < 512; i += 128) {
        int c = i & 127, h = i >> 7;
        s_WbT[h * 128 + c] = Wb[c * 4 + h];
    }
    __syncthreads();   // s_nb ready

    // k gather (float4 into stride-36 rows)
#pragma unroll
    for (int i = t; i < 256; i += 128) {
        int row = i >> 3, c4 = i & 7, nb = s_nb[row];
        float4 kv = *(const float4*)(g_k + (size_t)nb * 32 + c4 * 4);
        *(float4*)(&s_k[row][c4 * 4]) = kv;
    }
    // kp gather
#pragma unroll
    for (int i = t; i < 192; i += 128) {
        int row = i / 6, c4 = i % 6, nb = s_nb[row];
        float4 a4 = *(const float4*)(g_kp + (size_t)nb * 24 + c4 * 4);
        s_kp[row][c4*4+0]=a4.x; s_kp[row][c4*4+1]=a4.y; s_kp[row][c4*4+2]=a4.z; s_kp[row][c4*4+3]=a4.w;
    }
    CP_WAIT(0);
    __syncthreads();

    // pb partials: warp w -> heads {h0, h0+1}, column half [64*(w&1), +64).
    {
        const int half = warp & 1;
        const int h0   = (warp >> 1) << 1;
        const float4* prow = (const float4*)(s_pair + lane * 128 + half * 64);
        const float4* wr0  = (const float4*)(s_WbT + (h0 + 0) * 128 + half * 64);
        const float4* wr1  = (const float4*)(s_WbT + (h0 + 1) * 128 + half * 64);
        float pp0 = 0.f, pp1 = 0.f;
#pragma unroll
        for (int i = 0; i < 16; i++) {
            int c4 = (i + lane) & 15;
            float4 p  = prow[c4];
            float4 wa = wr0[c4];
            float4 wb = wr1[c4];
            pp0 += p.x * wa.x + p.y * wa.y + p.z * wa.z + p.w * wa.w;
            pp1 += p.x * wb.x + p.y * wb.y + p.z * wb.z + p.w * wb.w;
        }
        *(float2*)(s_pb2 + half * 128 + lane * 4 + h0) = make_float2(pp0, pp1);
    }
    __syncthreads();

    // ---- logits: head = warp, neighbour = lane ----
    const float w_L = 0.5773502691896258f;
    float gam   = gamma[warp];
    float scale = log1pf(__expf(gam)) * (1.0f / 6.0f) * 0.5f;

    // qk: vectorized float4 (8 iters x 2 LDS.128); small live set — no spill risk
    float qk = 0.f;
    {
        const float4* qrow = (const float4*)(s_q + warp * 32);
        const float4* krow = (const float4*)(&s_k[lane][0]);
#pragma unroll
        for (int c4 = 0; c4 < 8; c4++) {
            float4 qv = qrow[c4], kv = krow[c4];
            qk += qv.x * kv.x + qv.y * kv.y + qv.z * kv.z + qv.w * kv.w;
        }
    }

    // dist: scalar (vectorized version spills — R10)
    float dist = 0.f;
#pragma unroll
    for (int p = 0; p < 8; p++) {
        float dx = s_qp[warp * 24 + p * 3 + 0] - s_kp[lane][p * 3 + 0];
        float dy = s_qp[warp * 24 + p * 3 + 1] - s_kp[lane][p * 3 + 1];
        float dz = s_qp[warp * 24 + p * 3 + 2] - s_kp[lane][p * 3 + 2];
        dist += dx * dx + dy * dy + dz * dz;
    }

    float pb = s_pb2[lane * 4 + warp] + s_pb2[128 + lane * 4 + warp];

    float logit = w_L * (qk - scale * dist + pb);
    float m = warp_max(logit);
    float e = __expf(logit - m);
    float sm = warp_sum(e);
    s_attnT[lane * 4 + warp] = e / sm;    // [k][h]
    __syncthreads();

    float* conc = g_C + (size_t)n * KP2;

    // local_up
    {
        float acc = 0.f;
#pragma unroll
        for (int kk = 0; kk < 32; kk++)
            acc += s_attnT[kk * 4 + warp] * __ldg(g_v + (size_t)s_nb[kk] * 32 + lane);
        conc[warp * 32 + lane] = to_tf32(acc);
    }
    // pair_up (transposed): thread = column t, 4 heads
    {
        float a0 = 0.f, a1 = 0.f, a2 = 0.f, a3 = 0.f;
#pragma unroll
        for (int kk = 0; kk < 32; kk++) {
            float4 a4 = *(const float4*)(s_attnT + kk * 4);   // broadcast
            float pv = s_pair[kk * 128 + t];
            a0 += a4.x * pv; a1 += a4.y * pv; a2 += a4.z * pv; a3 += a4.w * pv;
        }
        conc[128 + 0 * 128 + t] = to_tf32(a0);
        conc[128 + 1 * 128 + t] = to_tf32(a1);
        conc[128 + 2 * 128 + t] = to_tf32(a2);
        conc[128 + 3 * 128 + t] = to_tf32(a3);
    }
    // pt sums
    if (t < 96) {
        int h = t / 24, j = t % 24;
        float acc = 0.f;
#pragma unroll
        for (int kk = 0; kk < 32; kk++)
            acc += s_attnT[kk * 4 + h] * __ldg(g_vp + (size_t)s_nb[kk] * 24 + j);
        s_pt[t] = acc;
    }
    if (t < 32) conc[736 + t] = 0.f;   // zero K-padding
    __syncthreads();
    if (t < 96) {
        int h = t / 24, pj = (t % 24) / 3, aidx = t % 3;
        const float* fr = frames + (size_t)n * 16;
        float r0 = fr[0 * 4 + aidx], r1 = fr[1 * 4 + aidx], r2 = fr[2 * 4 + aidx];
        float v0 = s_pt[h * 24 + pj * 3 + 0] - fr[0 * 4 + 3];
        float v1 = s_pt[h * 24 + pj * 3 + 1] - fr[1 * 4 + 3];
        float v2 = s_pt[h * 24 + pj * 3 + 2] - fr[2 * 4 + 3];
        conc[640 + t] = to_tf32(r0 * v0 + r1 * v1 + r2 * v2);
    }
}

// ---------------- launch ----------------
extern "C" void kernel_launch(void* const* d_in, const int* in_sizes, int n_in,
                              void* d_out, int out_size)
{
    const float* local      = (const float*)d_in[0];
    const float* pair       = (const float*)d_in[1];
    const float* frames     = (const float*)d_in[2];
    const int*   neighbours = (const int*)  d_in[3];
    // d_in[4] = mask (all-true by construction; identity)
    const float* Wq  = (const float*)d_in[5];
    const float* bq  = (const float*)d_in[6];
    const float* Wk  = (const float*)d_in[7];
    const float* bk  = (const float*)d_in[8];
    const float* Wv  = (const float*)d_in[9];
    const float* bv  = (const float*)d_in[10];
    const float* Wqp = (const float*)d_in[11];
    const float* bqp = (const float*)d_in[12];
    const float* Wkp = (const float*)d_in[13];
    const float* bkp = (const float*)d_in[14];
    const float* Wvp = (const float*)d_in[15];
    const float* bvp = (const float*)d_in[16];
    const float* Wb  = (const float*)d_in[17];
    const float* gamma = (const float*)d_in[18];
    const float* Wout  = (const float*)d_in[19];
    float* out = (float*)d_out;

    void *p_Atf, *p_WpT, *p_bias, *p_WoT, *p_C, *p_proj;
    cudaGetSymbolAddress(&p_Atf, g_Atf);
    cudaGetSymbolAddress(&p_WpT, g_WpT);
    cudaGetSymbolAddress(&p_bias, g_biasp);
    cudaGetSymbolAddress(&p_WoT, g_WoT);
    cudaGetSymbolAddress(&p_C, g_C);
    cudaGetSymbolAddress(&p_proj, g_proj);

    cudaFuncSetAttribute(mma_gemm, cudaFuncAttributeMaxDynamicSharedMemorySize, TGEMM_SMEM);

    // 0) local tf32 rounding + bias
    prep_local<<<2048, 256>>>(local, bq, bk, bv, bqp, bkp, bvp);

    // 1) Wproj transpose (coalesced tiles, tf32)
    prep_wpt<<<dim3(NPAD / 32, CLd / 32), dim3(32, 8)>>>(Wq, Wk, Wv, Wqp, Wkp, Wvp);

    // 2) Wout transpose (coalesced tiles, tf32)
    prep_wot<<<dim3(NPAD / 32, KP2 / 32), dim3(32, 8)>>>(Wout);

    // 3) proj = local @ Wproj + bias   (K=384, NC=6)   <- profile capture slot
    mma_gemm<<<dim3(2, 64), 512, TGEMM_SMEM>>>(
        (const float*)p_Atf, (const float*)p_WpT,
        (const float*)p_bias, (float*)p_proj, CLd);

    // 4) LN + frame transforms
    proj_epilogue<<<NN / 8, 256>>>(frames);

    // 5) attention -> tf32 concat
    attn_kernel<<<NN, 128>>>(pair, neighbours, frames, Wb, gamma);

    // 6) out = concat @ Wout   (K=768, NC=12)
    mma_gemm<<<dim3(2, 64), 512, TGEMM_SMEM>>>(
        (const float*)p_C, (const float*)p_WoT,
        nullptr, out, KP2);
}

// round 16
// speedup vs baseline: 1.2263x; 1.0485x over previous
#include <cuda_runtime.h>
#include <cuda_bf16.h>
#include <math.h>
#include <stdint.h>

// ---------------- problem constants ----------------
#define NN    8192
#define KNB   32
#define CLd   384
#define CPd   128
#define Hh    4
#define Sd    32
#define Pp    8
#define PROJ  336
#define NPAD  384
#define CONC  736
#define KP2   768

// ---------------- scratch (device globals; no allocation) ----------------
__device__ __align__(16) float g_Atf[NN * CLd];      // tf32-rounded local
__device__ __align__(16) float g_WpT[NPAD * CLd];    // tf32-rounded Wproj^T (padded)
__device__ __align__(16) float g_biasp[NPAD];
__device__ __align__(16) float g_WoT[NPAD * KP2];    // tf32-rounded Wout^T (padded)
__device__ __align__(16) float g_C[NN * KP2];        // tf32-rounded concat
__device__ __align__(16) float g_proj[NN * NPAD];
__device__ __align__(16) float g_q [NN * 128];
__device__ __align__(16) float g_k [NN * 32];
__device__ __align__(16) float g_v [NN * 32];
__device__ __align__(16) float g_qp[NN * 96];
__device__ __align__(16) float g_kp[NN * 24];
__device__ __align__(16) float g_vp[NN * 24];

// ---------------- PTX helpers ----------------
__device__ __forceinline__ uint32_t smem_u32(const void* p) {
    uint32_t a;
    asm("{ .reg .u64 t; cvta.to.shared.u64 t, %1; cvt.u32.u64 %0, t; }" : "=r"(a) : "l"(p));
    return a;
}
__device__ __forceinline__ float to_tf32(float x) {
    float r;
    asm("cvt.rna.tf32.f32 %0, %1;" : "=f"(r) : "f"(x));
    return r;
}

#define CP16(dst, src) \
    asm volatile("cp.async.cg.shared.global [%0], [%1], 16;" :: "r"(dst), "l"(src))
#define CP_COMMIT() asm volatile("cp.async.commit_group;" ::: "memory")
#define CP_WAIT(n)  asm volatile("cp.async.wait_group %0;" :: "n"(n) : "memory")

#define LDSM4(R, addr) \
    asm volatile("ldmatrix.sync.aligned.m8n8.x4.shared.b16 {%0,%1,%2,%3}, [%4];" \
        : "=r"((R)[0]), "=r"((R)[1]), "=r"((R)[2]), "=r"((R)[3]) : "r"(addr))

#define MMATF32(C, A, b0, b1) \
    asm volatile("mma.sync.aligned.m16n8k8.row.col.f32.tf32.tf32.f32 " \
        "{%0,%1,%2,%3}, {%4,%5,%6,%7}, {%8,%9}, {%0,%1,%2,%3};" \
        : "+f"((C)[0]), "+f"((C)[1]), "+f"((C)[2]), "+f"((C)[3]) \
        : "r"((A)[0]), "r"((A)[1]), "r"((A)[2]), "r"((A)[3]), "r"(b0), "r"(b1))

// ---------------- misc warp helpers ----------------
__device__ __forceinline__ float warp_sum(float v) {
#pragma unroll
    for (int o = 16; o; o >>= 1) v += __shfl_xor_sync(0xffffffffu, v, o);
    return v;
}
__device__ __forceinline__ float warp_max(float v) {
#pragma unroll
    for (int o = 16; o; o >>= 1) v = fmaxf(v, __shfl_xor_sync(0xffffffffu, v, o));
    return v;
}
__device__ __forceinline__ float2 warp_sum2(float a, float b) {
#pragma unroll
    for (int o = 16; o; o >>= 1) {
        a += __shfl_xor_sync(0xffffffffu, a, o);
        b += __shfl_xor_sync(0xffffffffu, b, o);
    }
    return make_float2(a, b);
}

// ---------------- fused prep kernel ----------------
// blocks [0,144): Wproj^T tiles; [144,432): Wout^T tiles; [432,2480): local split + bias
#define WPT_TILES 144          // 12 x 12
#define WOT_TILES 288          // 12 x 24
#define LOCAL_BLKS 2048
#define PREP_GRID (WPT_TILES + WOT_TILES + LOCAL_BLKS)

__global__ void __launch_bounds__(256) prep_fused(
    const float* __restrict__ local,
    const float* __restrict__ Wq,  const float* __restrict__ bq,
    const float* __restrict__ Wk,  const float* __restrict__ bk,
    const float* __restrict__ Wv,  const float* __restrict__ bv,
    const float* __restrict__ Wqp, const float* __restrict__ bqp,
    const float* __restrict__ Wkp, const float* __restrict__ bkp,
    const float* __restrict__ Wvp, const float* __restrict__ bvp,
    const float* __restrict__ Wout)
{
    __shared__ float tile[32][33];
    const int b  = blockIdx.x;
    const int tx = threadIdx.x & 31;
    const int ty = threadIdx.x >> 5;      // 0..7

    if (b < WPT_TILES) {
        const int n0 = (b % 12) * 32, k0 = (b / 12) * 32;
#pragma unroll
        for (int i = 0; i < 4; i++) {
            int k = k0 + ty + i * 8, n = n0 + tx;
            float w = 0.f;
            if      (n < 128) w = Wq [k * 128 + n];
            else if (n < 160) w = Wk [k * 32  + (n - 128)];
            else if (n < 192) w = Wv [k * 32  + (n - 160)];
            else if (n < 288) w = Wqp[k * 96  + (n - 192)];
            else if (n < 312) w = Wkp[k * 24  + (n - 288)];
            else if (n < 336) w = Wvp[k * 24  + (n - 312)];
            tile[ty + i * 8][tx] = w;
        }
        __syncthreads();
#pragma unroll
        for (int i = 0; i < 4; i++) {
            int n = n0 + ty + i * 8, k = k0 + tx;
            g_WpT[(size_t)n * CLd + k] = to_tf32(tile[tx][ty + i * 8]);
        }
    } else if (b < WPT_TILES + WOT_TILES) {
        const int bb = b - WPT_TILES;
        const int n0 = (bb % 12) * 32, k0 = (bb / 12) * 32;
#pragma unroll
        for (int i = 0; i < 4; i++) {
            int k = k0 + ty + i * 8, n = n0 + tx;
            float w = (k < CONC) ? Wout[(size_t)k * CLd + n] : 0.f;
            tile[ty + i * 8][tx] = w;
        }
        __syncthreads();
#pragma unroll
        for (int i = 0; i < 4; i++) {
            int n = n0 + ty + i * 8, k = k0 + tx;
            g_WoT[(size_t)n * KP2 + k] = to_tf32(tile[tx][ty + i * 8]);
        }
    } else {
        const int lb = b - WPT_TILES - WOT_TILES;    // 0..2047
        const int t  = threadIdx.x;
        const int total = NN * CLd;
        for (int idx = lb * 256 + t; idx < total; idx += LOCAL_BLKS * 256)
            g_Atf[idx] = to_tf32(local[idx]);
        if (lb == 0 && t < NPAD) {
            int n = t;
            float bias = 0.f;
            if      (n < 128) bias = bq [n];
            else if (n < 160) bias = bk [n - 128];
            else if (n < 192) bias = bv [n - 160];
            else if (n < 288) bias = bqp[n - 192];
            else if (n < 312) bias = bkp[n - 288];
            else if (n < 336) bias = bvp[n - 312];
            g_biasp[n] = bias;
        }
    }
}

// ---------------- tf32 HMMA GEMM: C[8192,384] = A @ B^T ----------------
// BM=128, BN=192, BK=64, 512 threads (4m x 4n warps, 32x48 warp tile), double-buffered.
#define TSTG_BYTES 87040
#define TOFF_B 34816
#define TGEMM_SMEM (2 * TSTG_BYTES)

__device__ __forceinline__ void issue_tile_f32(uint32_t sdst, const float* __restrict__ src,
                                               int K, int kk, int tid, int nchunks)
{
#pragma unroll
    for (int i = tid; i < nchunks; i += 512) {
        int r = i >> 4, c = i & 15;
        CP16(sdst + r * 272 + c * 16, src + (size_t)r * K + kk + c * 4);
    }
}

__global__ void __launch_bounds__(512, 1) mma_gemm(
    const float* __restrict__ A,
    const float* __restrict__ B,
    const float* __restrict__ bias, float* __restrict__ C, int K)
{
    extern __shared__ char dsm[];
    const uint32_t sbase = smem_u32(dsm);
    const int tid  = threadIdx.x;
    const int lane = tid & 31;
    const int wid  = tid >> 5;
    const int wm   = wid >> 2;
    const int wn   = wid & 3;
    const int rowBase = blockIdx.y * 128;
    const int colBase = blockIdx.x * 192;
    const int NC = K >> 6;

    const float* pA = A + (size_t)rowBase * K;
    const float* pB = B + (size_t)colBase * K;

    const uint32_t aoff = (uint32_t)((lane & 15) * 272 + ((lane >> 4) << 4));
    const uint32_t boff = (uint32_t)((((lane >> 4) * 8 + (lane & 7)) * 272) + (((lane >> 3) & 1) << 4));
    const uint32_t awbase = (uint32_t)(wm * 32 * 272);
    const uint32_t bwbase = (uint32_t)(wn * 48 * 272);

    float acc[2][6][4];
#pragma unroll
    for (int i = 0; i < 2; i++)
#pragma unroll
        for (int j = 0; j < 6; j++)
#pragma unroll
            for (int q = 0; q < 4; q++) acc[i][j][q] = 0.f;

    issue_tile_f32(sbase,          pA, K, 0, tid, 2048);
    issue_tile_f32(sbase + TOFF_B, pB, K, 0, tid, 3072);
    CP_COMMIT();

    for (int i = 0; i < NC; i++) {
        if (i + 1 < NC) {
            uint32_t st = sbase + (uint32_t)((i + 1) & 1) * TSTG_BYTES;
            int kk = (i + 1) << 6;
            issue_tile_f32(st,          pA, K, kk, tid, 2048);
            issue_tile_f32(st + TOFF_B, pB, K, kk, tid, 3072);
            CP_COMMIT();
            CP_WAIT(1);
        } else {
            CP_WAIT(0);
        }
        __syncthreads();

        const uint32_t st = sbase + (uint32_t)(i & 1) * TSTG_BYTES;
        const uint32_t sA = st + awbase;
        const uint32_t sB = st + TOFF_B + bwbase;

#pragma unroll
        for (int s = 0; s < 8; s++) {
            const uint32_t ka = (uint32_t)(s * 32);
            uint32_t av[8], bv[12];
            LDSM4(av,     sA + ka + aoff);
            LDSM4(av + 4, sA + 16 * 272 + ka + aoff);
#pragma unroll
            for (int L = 0; L < 3; L++)
                LDSM4(bv + L * 4, sB + (uint32_t)(L * 16 * 272) + ka + boff);
#pragma unroll
            for (int mf = 0; mf < 2; mf++) {
#pragma unroll
                for (int nt = 0; nt < 6; nt++) {
                    const int L = nt >> 1, h = (nt & 1) * 2;
                    MMATF32(acc[mf][nt], av + mf * 4, bv[L * 4 + h], bv[L * 4 + h + 1]);
                }
            }
        }
        __syncthreads();
    }

    const int r0 = lane >> 2;
    const int c0 = (lane & 3) * 2;
#pragma unroll
    for (int mf = 0; mf < 2; mf++) {
#pragma unroll
        for (int nt = 0; nt < 6; nt++) {
            int row = rowBase + wm * 32 + mf * 16 + r0;
            int col = colBase + wn * 48 + nt * 8 + c0;
            float b0 = 0.f, b1 = 0.f;
            if (bias) { b0 = bias[col]; b1 = bias[col + 1]; }
            float2 v0 = make_float2(acc[mf][nt][0] + b0, acc[mf][nt][1] + b1);
            float2 v1 = make_float2(acc[mf][nt][2] + b0, acc[mf][nt][3] + b1);
            *(float2*)(C + (size_t)row * NPAD + col)       = v0;
            *(float2*)(C + (size_t)(row + 8) * NPAD + col) = v1;
        }
    }
}

// ---------------- kernel: LN + frame transforms ----------------
__global__ void __launch_bounds__(256) proj_epilogue(const float* __restrict__ frames)
{
    const int warp = threadIdx.x >> 5;
    const int lane = threadIdx.x & 31;
    const int n = blockIdx.x * 8 + warp;
    if (n >= NN) return;
    const float* pr = g_proj + (size_t)n * NPAD;
    const float inv_sqrtS = 0.17677669529663687f;

#pragma unroll
    for (int h = 0; h < Hh; h++) {
        float x  = pr[h * 32 + lane];
        float2 s = warp_sum2(x, x * x);
        float mu = s.x * (1.f / 32.f);
        float var = s.y * (1.f / 32.f) - mu * mu;
        g_q[(size_t)n * 128 + h * 32 + lane] = (x - mu) * rsqrtf(var + 1e-5f) * inv_sqrtS;
    }
    {
        float x  = pr[128 + lane];
        float2 s = warp_sum2(x, x * x);
        float mu = s.x * (1.f / 32.f);
        float var = s.y * (1.f / 32.f) - mu * mu;
        g_k[(size_t)n * 32 + lane] = (x - mu) * rsqrtf(var + 1e-5f);
    }
    g_v[(size_t)n * 32 + lane] = pr[160 + lane];

    const float* fr = frames + (size_t)n * 16;
    float R00 = fr[0],  R01 = fr[1],  R02 = fr[2],  t0 = fr[3];
    float R10 = fr[4],  R11 = fr[5],  R12 = fr[6],  t1 = fr[7];
    float R20 = fr[8],  R21 = fr[9],  R22 = fr[10], t2 = fr[11];

    {
        float px = pr[192 + lane * 3 + 0];
        float py = pr[192 + lane * 3 + 1];
        float pz = pr[192 + lane * 3 + 2];
        float* q = g_qp + (size_t)n * 96 + lane * 3;
        q[0] = R00 * px + R01 * py + R02 * pz + t0;
        q[1] = R10 * px + R11 * py + R12 * pz + t1;
        q[2] = R20 * px + R21 * py + R22 * pz + t2;
    }
    if (lane < 8) {
        float px = pr[288 + lane * 3 + 0];
        float py = pr[288 + lane * 3 + 1];
        float pz = pr[288 + lane * 3 + 2];
        float* q = g_kp + (size_t)n * 24 + lane * 3;
        q[0] = R00 * px + R01 * py + R02 * pz + t0;
        q[1] = R10 * px + R11 * py + R12 * pz + t1;
        q[2] = R20 * px + R21 * py + R22 * pz + t2;
    } else if (lane < 16) {
        int l2 = lane - 8;
        float px = pr[312 + l2 * 3 + 0];
        float py = pr[312 + l2 * 3 + 1];
        float pz = pr[312 + l2 * 3 + 2];
        float* q = g_vp + (size_t)n * 24 + l2 * 3;
        q[0] = R00 * px + R01 * py + R02 * pz + t0;
        q[1] = R10 * px + R11 * py + R12 * pz + t1;
        q[2] = R20 * px + R21 * py + R22 * pz + t2;
    }
}

// ---------------- kernel: attention (R15 + float4 dist under unroll-1 guard) ----------------
__global__ void __launch_bounds__(128, 7) attn_kernel(
    const float* __restrict__ pair,        // N*K*CP
    const int*   __restrict__ neighbours,  // N*K
    const float* __restrict__ frames,      // N*16
    const float* __restrict__ Wb,          // CP*H
    const float* __restrict__ gamma)       // H
{
    const int n    = blockIdx.x;
    const int t    = threadIdx.x;
    const int lane = t & 31;
    const int warp = t >> 5;

    __shared__ __align__(16) float s_q[128];
    __shared__ __align__(16) float s_qp[96];
    __shared__ int   s_nb[32];
    __shared__ __align__(16) float s_k [32][36];   // stride 36: float4, conflict-free
    __shared__ __align__(16) float s_kp[32][28];   // stride 28: float4, conflict-free
    __shared__ __align__(16) float s_pair[32 * 128];
    __shared__ __align__(16) float s_WbT[4 * 128];
    __shared__ __align__(16) float s_pb2[2 * 128];    // [half][k*4+h]
    __shared__ __align__(16) float s_attnT[32 * 4];   // [k][h]
    __shared__ float s_pt[96];

    // async pair load (16KB) — overlaps gathers
    {
        const uint32_t sp = smem_u32(s_pair);
        const float* psrc = pair + (size_t)n * 4096;
#pragma unroll
        for (int j = 0; j < 8; j++) {
            int i = t + 128 * j;
            CP16(sp + (uint32_t)i * 16, psrc + i * 4);
        }
        CP_COMMIT();
    }

    if (t < 32) s_nb[t] = neighbours[(size_t)n * 32 + t];
    s_q[t] = g_q[(size_t)n * 128 + t];
    if (t < 96) s_qp[t] = g_qp[(size_t)n * 96 + t];
    for (int i = t; i < 512; i += 128) {
        int c = i & 127, h = i >> 7;
        s_WbT[h * 128 + c] = Wb[c * 4 + h];
    }
    __syncthreads();   // s_nb ready

    // k gather (float4 into stride-36 rows)
#pragma unroll
    for (int i = t; i < 256; i += 128) {
        int row = i >> 3, c4 = i & 7, nb = s_nb[row];
        float4 kv = *(const float4*)(g_k + (size_t)nb * 32 + c4 * 4);
        *(float4*)(&s_k[row][c4 * 4]) = kv;
    }
    // kp gather (float4 into stride-28 rows)
#pragma unroll
    for (int i = t; i < 192; i += 128) {
        int row = i / 6, c4 = i % 6, nb = s_nb[row];
        float4 a4 = *(const float4*)(g_kp + (size_t)nb * 24 + c4 * 4);
        *(float4*)(&s_kp[row][c4 * 4]) = a4;
    }
    CP_WAIT(0);
    __syncthreads();

    // pb partials: warp w -> heads {h0, h0+1}, column half [64*(w&1), +64).
    {
        const int half = warp & 1;
        const int h0   = (warp >> 1) << 1;
        const float4* prow = (const float4*)(s_pair + lane * 128 + half * 64);
        const float4* wr0  = (const float4*)(s_WbT + (h0 + 0) * 128 + half * 64);
        const float4* wr1  = (const float4*)(s_WbT + (h0 + 1) * 128 + half * 64);
        float pp0 = 0.f, pp1 = 0.f;
#pragma unroll
        for (int i = 0; i < 16; i++) {
            int c4 = (i + lane) & 15;
            float4 p  = prow[c4];
            float4 wa = wr0[c4];
            float4 wb = wr1[c4];
            pp0 += p.x * wa.x + p.y * wa.y + p.z * wa.z + p.w * wa.w;
            pp1 += p.x * wb.x + p.y * wb.y + p.z * wb.z + p.w * wb.w;
        }
        *(float2*)(s_pb2 + half * 128 + lane * 4 + h0) = make_float2(pp0, pp1);
    }
    __syncthreads();

    // ---- logits: head = warp, neighbour = lane ----
    const float w_L = 0.5773502691896258f;
    float gam   = gamma[warp];
    float scale = log1pf(__expf(gam)) * (1.0f / 6.0f) * 0.5f;

    // qk: float4 (proven safe in R15)
    float qk = 0.f;
    {
        const float4* qrow = (const float4*)(s_q + warp * 32);
        const float4* krow = (const float4*)(&s_k[lane][0]);
#pragma unroll
        for (int c4 = 0; c4 < 8; c4++) {
            float4 qv = qrow[c4], kv = krow[c4];
            qk += qv.x * kv.x + qv.y * kv.y + qv.z * kv.z + qv.w * kv.w;
        }
    }

    // dist: float4 with unroll-1 guard (prevents load hoisting -> no spill; R10 lesson)
    float dist = 0.f;
    {
        const float4* kpr = (const float4*)(&s_kp[lane][0]);
        const float4* qpr = (const float4*)(s_qp + warp * 24);
#pragma unroll 1
        for (int c4 = 0; c4 < 6; c4++) {
            float4 a = qpr[c4], b = kpr[c4];
            float dx = a.x - b.x, dy = a.y - b.y, dz = a.z - b.z, dw = a.w - b.w;
            dist += dx * dx + dy * dy + dz * dz + dw * dw;
        }
    }

    float pb = s_pb2[lane * 4 + warp] + s_pb2[128 + lane * 4 + warp];

    float logit = w_L * (qk - scale * dist + pb);
    float m = warp_max(logit);
    float e = __expf(logit - m);
    float sm = warp_sum(e);
    s_attnT[lane * 4 + warp] = e / sm;    // [k][h]
    __syncthreads();

    float* conc = g_C + (size_t)n * KP2;

    // local_up
    {
        float acc = 0.f;
#pragma unroll
        for (int kk = 0; kk < 32; kk++)
            acc += s_attnT[kk * 4 + warp] * __ldg(g_v + (size_t)s_nb[kk] * 32 + lane);
        conc[warp * 32 + lane] = to_tf32(acc);
    }
    // pair_up (transposed): thread = column t, 4 heads
    {
        float a0 = 0.f, a1 = 0.f, a2 = 0.f, a3 = 0.f;
#pragma unroll
        for (int kk = 0; kk < 32; kk++) {
            float4 a4 = *(const float4*)(s_attnT + kk * 4);   // broadcast
            float pv = s_pair[kk * 128 + t];
            a0 += a4.x * pv; a1 += a4.y * pv; a2 += a4.z * pv; a3 += a4.w * pv;
        }
        conc[128 + 0 * 128 + t] = to_tf32(a0);
        conc[128 + 1 * 128 + t] = to_tf32(a1);
        conc[128 + 2 * 128 + t] = to_tf32(a2);
        conc[128 + 3 * 128 + t] = to_tf32(a3);
    }
    // pt sums
    if (t < 96) {
        int h = t / 24, j = t % 24;
        float acc = 0.f;
#pragma unroll
        for (int kk = 0; kk < 32; kk++)
            acc += s_attnT[kk * 4 + h] * __ldg(g_vp + (size_t)s_nb[kk] * 24 + j);
        s_pt[t] = acc;
    }
    if (t < 32) conc[736 + t] = 0.f;   // zero K-padding
    __syncthreads();
    if (t < 96) {
        int h = t / 24, pj = (t % 24) / 3, aidx = t % 3;
        const float* fr = frames + (size_t)n * 16;
        float r0 = fr[0 * 4 + aidx], r1 = fr[1 * 4 + aidx], r2 = fr[2 * 4 + aidx];
        float v0 = s_pt[h * 24 + pj * 3 + 0] - fr[0 * 4 + 3];
        float v1 = s_pt[h * 24 + pj * 3 + 1] - fr[1 * 4 + 3];
        float v2 = s_pt[h * 24 + pj * 3 + 2] - fr[2 * 4 + 3];
        conc[640 + t] = to_tf32(r0 * v0 + r1 * v1 + r2 * v2);
    }
}

// ---------------- launch ----------------
extern "C" void kernel_launch(void* const* d_in, const int* in_sizes, int n_in,
                              void* d_out, int out_size)
{
    const float* local      = (const float*)d_in[0];
    const float* pair       = (const float*)d_in[1];
    const float* frames     = (const float*)d_in[2];
    const int*   neighbours = (const int*)  d_in[3];
    // d_in[4] = mask (all-true by construction; identity)
    const float* Wq  = (const float*)d_in[5];
    const float* bq  = (const float*)d_in[6];
    const float* Wk  = (const float*)d_in[7];
    const float* bk  = (const float*)d_in[8];
    const float* Wv  = (const float*)d_in[9];
    const float* bv  = (const float*)d_in[10];
    const float* Wqp = (const float*)d_in[11];
    const float* bqp = (const float*)d_in[12];
    const float* Wkp = (const float*)d_in[13];
    const float* bkp = (const float*)d_in[14];
    const float* Wvp = (const float*)d_in[15];
    const float* bvp = (const float*)d_in[16];
    const float* Wb  = (const float*)d_in[17];
    const float* gamma = (const float*)d_in[18];
    const float* Wout  = (const float*)d_in[19];
    float* out = (float*)d_out;

    void *p_Atf, *p_WpT, *p_bias, *p_WoT, *p_C, *p_proj;
    cudaGetSymbolAddress(&p_Atf, g_Atf);
    cudaGetSymbolAddress(&p_WpT, g_WpT);
    cudaGetSymbolAddress(&p_bias, g_biasp);
    cudaGetSymbolAddress(&p_WoT, g_WoT);
    cudaGetSymbolAddress(&p_C, g_C);
    cudaGetSymbolAddress(&p_proj, g_proj);

    cudaFuncSetAttribute(mma_gemm, cudaFuncAttributeMaxDynamicSharedMemorySize, TGEMM_SMEM);

    // 0) fused prep: weight transposes + local tf32 + bias (one launch)
    prep_fused<<<PREP_GRID, 256>>>(local, Wq, bq, Wk, bk, Wv, bv,
                                   Wqp, bqp, Wkp, bkp, Wvp, bvp, Wout);

    // 1) proj = local @ Wproj + bias   (K=384, NC=6)
    mma_gemm<<<dim3(2, 64), 512, TGEMM_SMEM>>>(
        (const float*)p_Atf, (const float*)p_WpT,
        (const float*)p_bias, (float*)p_proj, CLd);

    // 2) LN + frame transforms
    proj_epilogue<<<NN / 8, 256>>>(frames);

    // 3) attention -> tf32 concat
    attn_kernel<<<NN, 128>>>(pair, neighbours, frames, Wb, gamma);

    // 4) out = concat @ Wout   (K=768, NC=12)
    mma_gemm<<<dim3(2, 64), 512, TGEMM_SMEM>>>(
        (const float*)p_C, (const float*)p_WoT,
        nullptr, out, KP2);
}